// round 1
// baseline (speedup 1.0000x reference)
#include <cuda_runtime.h>

// ---------------------------------------------------------------------------
// StressGNN: 2-layer GCN + mean readout + FC, restructured as
//   deg/dinv -> CSR build -> agg(x) -> @W1+b1,relu -> agg(.) -> @W2+b2,relu
//   fused with (1/N)*sum_i( . @ Wfc ) + bfc
// Aggregation commutes with the per-layer linear map, so we aggregate in the
// INPUT feature dim of each layer (8 and 64 floats/edge instead of 64/128).
// ---------------------------------------------------------------------------

#define N_MAX 100000
#define E_MAX 1600000

// __device__ scratch (allocation-free per harness rules)
__device__ int    g_deg[N_MAX];          // in-degree + 1 (self loop)
__device__ int    g_row_start[N_MAX];    // CSR row starts (bucket base)
__device__ int    g_cursor[N_MAX];       // scatter cursors
__device__ int    g_col[E_MAX];          // src of edges grouped by dst
__device__ float  g_dinv[N_MAX];         // deg^-1/2
__device__ float4 g_g0[2 * N_MAX];       // dinv[i] * x[i]            [N,8]
__device__ float4 g_a1[2 * N_MAX];       // layer-1 aggregated input   [N,8]
__device__ float4 g_g1[16 * N_MAX];      // dinv[i] * relu(a1@W1+b1)   [N,64]
__device__ float4 g_a2[16 * N_MAX];      // layer-2 aggregated input   [N,64]
__device__ int    g_counter;             // CSR base allocator
__device__ float  g_total;               // readout accumulator

__device__ __forceinline__ float4 f4add(float4 a, float4 b) {
    return make_float4(a.x + b.x, a.y + b.y, a.z + b.z, a.w + b.w);
}
__device__ __forceinline__ float4 f4scale(float s, float4 a) {
    return make_float4(s * a.x, s * a.y, s * a.z, s * a.w);
}

// ---------------------------------------------------------------------------
__global__ void k_init(int n) {
    int i = blockIdx.x * blockDim.x + threadIdx.x;
    if (i < n) g_deg[i] = 1;  // self loop
    if (i == 0) { g_counter = 0; g_total = 0.0f; }
}

__global__ void k_hist(const int* __restrict__ ei, int E) {
    int e = blockIdx.x * blockDim.x + threadIdx.x;
    if (e >= E) return;
    atomicAdd(&g_deg[ei[E + e]], 1);   // dst row of edge_index
}

// block-local scan + atomic base allocation -> CSR row starts
__global__ void k_scan(int n) {
    __shared__ int sh[1024];
    __shared__ int s_base;
    int tid = threadIdx.x;
    int i = blockIdx.x * 1024 + tid;
    int c = (i < n) ? (g_deg[i] - 1) : 0;
    sh[tid] = c;
    __syncthreads();
    for (int off = 1; off < 1024; off <<= 1) {
        int v = (tid >= off) ? sh[tid - off] : 0;
        __syncthreads();
        sh[tid] += v;
        __syncthreads();
    }
    if (tid == 0) s_base = atomicAdd(&g_counter, sh[1023]);
    __syncthreads();
    int rs = s_base + sh[tid] - c;   // exclusive within block + global base
    if (i < n) { g_row_start[i] = rs; g_cursor[i] = rs; }
}

__global__ void k_scatter(const int* __restrict__ ei, int E) {
    int e = blockIdx.x * blockDim.x + threadIdx.x;
    if (e >= E) return;
    int s = ei[e];
    int d = ei[E + e];
    int pos = atomicAdd(&g_cursor[d], 1);
    g_col[pos] = s;
}

__global__ void k_dinv_g0(const float* __restrict__ x, int n) {
    int i = blockIdx.x * blockDim.x + threadIdx.x;
    if (i >= n) return;
    float di = rsqrtf((float)g_deg[i]);
    g_dinv[i] = di;
    const float4* x4 = (const float4*)x;
    g_g0[2 * i]     = f4scale(di, x4[2 * i]);
    g_g0[2 * i + 1] = f4scale(di, x4[2 * i + 1]);
}

// ---------------------------------------------------------------------------
// agg1: a1[d] = dinv[d] * ( sum_{e:dst=d} g0[src] + g0[d] ), 8 floats/node
__global__ void k_agg1(int n) {
    int i = blockIdx.x * blockDim.x + threadIdx.x;
    if (i >= n) return;
    float4 aL = g_g0[2 * i];
    float4 aH = g_g0[2 * i + 1];
    float4 bL = make_float4(0, 0, 0, 0);
    float4 bH = make_float4(0, 0, 0, 0);
    int st = g_row_start[i];
    int cnt = g_deg[i] - 1;
    int j = 0;
    for (; j + 4 <= cnt; j += 4) {
        int s0 = g_col[st + j], s1 = g_col[st + j + 1];
        int s2 = g_col[st + j + 2], s3 = g_col[st + j + 3];
        aL = f4add(aL, g_g0[2 * s0]);     aH = f4add(aH, g_g0[2 * s0 + 1]);
        bL = f4add(bL, g_g0[2 * s1]);     bH = f4add(bH, g_g0[2 * s1 + 1]);
        aL = f4add(aL, g_g0[2 * s2]);     aH = f4add(aH, g_g0[2 * s2 + 1]);
        bL = f4add(bL, g_g0[2 * s3]);     bH = f4add(bH, g_g0[2 * s3 + 1]);
    }
    for (; j < cnt; j++) {
        int s = g_col[st + j];
        aL = f4add(aL, g_g0[2 * s]);      aH = f4add(aH, g_g0[2 * s + 1]);
    }
    aL = f4add(aL, bL); aH = f4add(aH, bH);
    float di = g_dinv[i];
    g_a1[2 * i]     = f4scale(di, aL);
    g_a1[2 * i + 1] = f4scale(di, aH);
}

// ---------------------------------------------------------------------------
// gemm1: g1[i] = dinv[i] * relu(a1[i] @ W1 + b1)   [N,64]
__global__ void k_gemm1(const float* __restrict__ W1, const float* __restrict__ b1, int n) {
    __shared__ float W1s[8 * 64];
    __shared__ float b1s[64];
    int tid = threadIdx.x;
    for (int t = tid; t < 512; t += blockDim.x) W1s[t] = W1[t];
    if (tid < 64) b1s[tid] = b1[tid];
    __syncthreads();
    int i = blockIdx.x * blockDim.x + tid;
    if (i >= n) return;
    float a[8];
    float4 v0 = g_a1[2 * i], v1 = g_a1[2 * i + 1];
    a[0] = v0.x; a[1] = v0.y; a[2] = v0.z; a[3] = v0.w;
    a[4] = v1.x; a[5] = v1.y; a[6] = v1.z; a[7] = v1.w;
    float di = g_dinv[i];
    float4* out = &g_g1[i * 16];
#pragma unroll
    for (int t4 = 0; t4 < 16; t4++) {
        float r0 = b1s[4 * t4], r1 = b1s[4 * t4 + 1];
        float r2 = b1s[4 * t4 + 2], r3 = b1s[4 * t4 + 3];
#pragma unroll
        for (int k = 0; k < 8; k++) {
            float ak = a[k];
            const float* wr = &W1s[k * 64 + 4 * t4];
            r0 += ak * wr[0]; r1 += ak * wr[1];
            r2 += ak * wr[2]; r3 += ak * wr[3];
        }
        out[t4] = make_float4(di * fmaxf(r0, 0.0f), di * fmaxf(r1, 0.0f),
                              di * fmaxf(r2, 0.0f), di * fmaxf(r3, 0.0f));
    }
}

// ---------------------------------------------------------------------------
// agg2: warp per node; a2[d] = dinv[d] * ( sum g1[src] + g1[d] ), 64 floats
__global__ void k_agg2(int n) {
    int gtid = blockIdx.x * blockDim.x + threadIdx.x;
    int node = gtid >> 5;
    int lane = gtid & 31;
    if (node >= n) return;
    const float2* g1 = (const float2*)g_g1;
    float2 acc = g1[node * 32 + lane];   // self loop
    int st = g_row_start[node];
    int cnt = g_deg[node] - 1;
    for (int base = 0; base < cnt; base += 32) {
        int idx = base + lane;
        int s = (idx < cnt) ? g_col[st + idx] : 0;
        int m = cnt - base; if (m > 32) m = 32;
        for (int j = 0; j < m; j++) {
            int sj = __shfl_sync(0xffffffffu, s, j);
            float2 v = g1[sj * 32 + lane];  // 32 lanes -> contiguous 256B row
            acc.x += v.x; acc.y += v.y;
        }
    }
    float di = g_dinv[node];
    ((float2*)g_a2)[node * 32 + lane] = make_float2(di * acc.x, di * acc.y);
}

// ---------------------------------------------------------------------------
// gemm2 + fused readout:
//   nodesum_i = sum_c relu( (a2[i]@W2)_c + b2_c ) * Wfc_c ;  g_total += sum_i
// Packed FP32 (fma.rn.f32x2) for 2x FFMA throughput.
__global__ void __launch_bounds__(256)
k_gemm2_reduce(const float* __restrict__ W2, const float* __restrict__ b2,
               const float* __restrict__ Wfc, int n) {
    __shared__ float W2s[64 * 128];   // 32 KB
    __shared__ float b2s[128];
    __shared__ float wfs[128];
    __shared__ float red[256];
    int tid = threadIdx.x;
    for (int t = tid; t < 2048; t += blockDim.x)
        ((float4*)W2s)[t] = ((const float4*)W2)[t];
    if (tid < 128) { b2s[tid] = b2[tid]; wfs[tid] = Wfc[tid]; }
    __syncthreads();

    int i = blockIdx.x * blockDim.x + tid;
    float nodesum = 0.0f;
    if (i < n) {
        float a[64];
        const float4* ar = &g_a2[i * 16];
#pragma unroll
        for (int t = 0; t < 16; t++) {
            float4 v = ar[t];
            a[4 * t] = v.x; a[4 * t + 1] = v.y; a[4 * t + 2] = v.z; a[4 * t + 3] = v.w;
        }
        for (int ch = 0; ch < 4; ch++) {     // 4 chunks of 32 output cols
            unsigned long long acc[16];
#pragma unroll
            for (int t = 0; t < 16; t++) acc[t] = 0ull;
#pragma unroll
            for (int k = 0; k < 64; k++) {
                unsigned int au = __float_as_uint(a[k]);
                unsigned long long ap;
                asm("mov.b64 %0, {%1, %1};" : "=l"(ap) : "r"(au));
                const ulonglong2* w =
                    reinterpret_cast<const ulonglong2*>(&W2s[k * 128 + ch * 32]);
#pragma unroll
                for (int t = 0; t < 8; t++) {
                    ulonglong2 wv = w[t];   // LDS.128 broadcast (all lanes same addr)
                    asm("fma.rn.f32x2 %0, %1, %2, %0;"
                        : "+l"(acc[2 * t]) : "l"(ap), "l"(wv.x));
                    asm("fma.rn.f32x2 %0, %1, %2, %0;"
                        : "+l"(acc[2 * t + 1]) : "l"(ap), "l"(wv.y));
                }
            }
#pragma unroll
            for (int u = 0; u < 16; u++) {
                unsigned int lo_u, hi_u;
                asm("mov.b64 {%0, %1}, %2;" : "=r"(lo_u), "=r"(hi_u) : "l"(acc[u]));
                int c = ch * 32 + 2 * u;
                float v0 = fmaxf(__uint_as_float(lo_u) + b2s[c], 0.0f);
                float v1 = fmaxf(__uint_as_float(hi_u) + b2s[c + 1], 0.0f);
                nodesum += v0 * wfs[c] + v1 * wfs[c + 1];
            }
        }
    }
    red[tid] = nodesum;
    __syncthreads();
    for (int off = 128; off > 0; off >>= 1) {
        if (tid < off) red[tid] += red[tid + off];
        __syncthreads();
    }
    if (tid == 0) atomicAdd(&g_total, red[0]);
}

__global__ void k_final(const float* __restrict__ bfc, float* __restrict__ out, float invn) {
    out[0] = g_total * invn + bfc[0];
}

// ---------------------------------------------------------------------------
extern "C" void kernel_launch(void* const* d_in, const int* in_sizes, int n_in,
                              void* d_out, int out_size) {
    const float* x   = (const float*)d_in[0];
    const int*   ei  = (const int*)  d_in[1];
    const float* W1  = (const float*)d_in[2];
    const float* b1  = (const float*)d_in[3];
    const float* W2  = (const float*)d_in[4];
    const float* b2  = (const float*)d_in[5];
    const float* Wfc = (const float*)d_in[6];
    const float* bfc = (const float*)d_in[7];

    int n = in_sizes[0] / 8;
    int E = in_sizes[1] / 2;
    if (n > N_MAX) n = N_MAX;
    if (E > E_MAX) E = E_MAX;

    int nb  = (n + 255) / 256;
    int eb  = (E + 255) / 256;
    int sb  = (n + 1023) / 1024;
    int wb  = (n * 32 + 255) / 256;   // warp per node

    k_init        <<<nb, 256>>>(n);
    k_hist        <<<eb, 256>>>(ei, E);
    k_scan        <<<sb, 1024>>>(n);
    k_scatter     <<<eb, 256>>>(ei, E);
    k_dinv_g0     <<<nb, 256>>>(x, n);
    k_agg1        <<<nb, 256>>>(n);
    k_gemm1       <<<nb, 256>>>(W1, b1, n);
    k_agg2        <<<wb, 256>>>(n);
    k_gemm2_reduce<<<nb, 256>>>(W2, b2, Wfc, n);
    k_final       <<<1, 1>>>(bfc, (float*)d_out, 1.0f / (float)n);
}

// round 2
// speedup vs baseline: 1.0106x; 1.0106x over previous
#include <cuda_runtime.h>
#include <cuda_bf16.h>

// ---------------------------------------------------------------------------
// StressGNN: 2-layer GCN + mean readout + FC.
//   deg/dinv -> CSR build -> [agg1+gemm1 fused] -> agg2 (bf16 gather) ->
//   [gemm2 + relu + Wfc-dot + mean-reduce fused]
// Aggregation commutes with each layer's linear map -> aggregate in the INPUT
// feature dim (8 and 64 floats/edge). g1 stored in bf16 to halve agg2's L2
// gather traffic (the dominant memory term).
// ---------------------------------------------------------------------------

#define N_MAX 100000
#define E_MAX 1600000

__device__ int    g_deg[N_MAX];              // in-degree + 1 (self loop)
__device__ int    g_row_start[N_MAX];        // CSR row starts
__device__ int    g_cursor[N_MAX];           // scatter cursors
__device__ int    g_col[E_MAX];              // src grouped by dst
__device__ float  g_dinv[N_MAX];             // deg^-1/2
__device__ float4 g_g0[2 * N_MAX];           // dinv[i] * x[i]            [N,8]
__device__ __nv_bfloat162 g_g1b[32 * N_MAX]; // dinv[i]*relu(a1@W1+b1)    [N,64] bf16
__device__ float4 g_a2[16 * N_MAX];          // layer-2 aggregated input  [N,64]
__device__ int    g_counter;
__device__ float  g_total;

__device__ __forceinline__ float4 f4add(float4 a, float4 b) {
    return make_float4(a.x + b.x, a.y + b.y, a.z + b.z, a.w + b.w);
}
__device__ __forceinline__ float4 f4scale(float s, float4 a) {
    return make_float4(s * a.x, s * a.y, s * a.z, s * a.w);
}

// ---------------------------------------------------------------------------
__global__ void k_init(int n) {
    int i = blockIdx.x * blockDim.x + threadIdx.x;
    if (i < n) g_deg[i] = 1;  // self loop
    if (i == 0) { g_counter = 0; g_total = 0.0f; }
}

__global__ void k_hist(const int* __restrict__ ei, int E) {
    int e = blockIdx.x * blockDim.x + threadIdx.x;
    if (e >= E) return;
    atomicAdd(&g_deg[ei[E + e]], 1);
}

// block scan + atomic base -> CSR row starts; also dinv + g0 (deg is final here)
__global__ void k_scan_dinv_g0(const float* __restrict__ x, int n) {
    __shared__ int sh[1024];
    __shared__ int s_base;
    int tid = threadIdx.x;
    int i = blockIdx.x * 1024 + tid;
    int deg = (i < n) ? g_deg[i] : 1;
    int c = deg - 1;
    sh[tid] = c;
    __syncthreads();
    for (int off = 1; off < 1024; off <<= 1) {
        int v = (tid >= off) ? sh[tid - off] : 0;
        __syncthreads();
        sh[tid] += v;
        __syncthreads();
    }
    if (tid == 0) s_base = atomicAdd(&g_counter, sh[1023]);
    __syncthreads();
    int rs = s_base + sh[tid] - c;
    if (i < n) {
        g_row_start[i] = rs;
        g_cursor[i] = rs;
        float di = rsqrtf((float)deg);
        g_dinv[i] = di;
        const float4* x4 = (const float4*)x;
        g_g0[2 * i]     = f4scale(di, x4[2 * i]);
        g_g0[2 * i + 1] = f4scale(di, x4[2 * i + 1]);
    }
}

__global__ void k_scatter(const int* __restrict__ ei, int E) {
    int e = blockIdx.x * blockDim.x + threadIdx.x;
    if (e >= E) return;
    int s = ei[e];
    int d = ei[E + e];
    int pos = atomicAdd(&g_cursor[d], 1);
    g_col[pos] = s;
}

// ---------------------------------------------------------------------------
// Fused layer 1: a1 = dinv*(sum g0[src] + g0[self]); g1 = bf16(dinv*relu(a1@W1+b1))
__global__ void __launch_bounds__(256)
k_agg1_gemm1(const float* __restrict__ W1, const float* __restrict__ b1, int n) {
    __shared__ float W1s[8 * 64];
    __shared__ float b1s[64];
    int tid = threadIdx.x;
    for (int t = tid; t < 512; t += blockDim.x) W1s[t] = W1[t];
    if (tid < 64) b1s[tid] = b1[tid];
    __syncthreads();

    int i = blockIdx.x * blockDim.x + tid;
    if (i >= n) return;

    // ---- agg1 ----
    float4 aL = g_g0[2 * i];
    float4 aH = g_g0[2 * i + 1];
    float4 bL = make_float4(0, 0, 0, 0);
    float4 bH = make_float4(0, 0, 0, 0);
    int st = g_row_start[i];
    int cnt = g_deg[i] - 1;
    int j = 0;
    for (; j + 4 <= cnt; j += 4) {
        int s0 = g_col[st + j], s1 = g_col[st + j + 1];
        int s2 = g_col[st + j + 2], s3 = g_col[st + j + 3];
        aL = f4add(aL, g_g0[2 * s0]);  aH = f4add(aH, g_g0[2 * s0 + 1]);
        bL = f4add(bL, g_g0[2 * s1]);  bH = f4add(bH, g_g0[2 * s1 + 1]);
        aL = f4add(aL, g_g0[2 * s2]);  aH = f4add(aH, g_g0[2 * s2 + 1]);
        bL = f4add(bL, g_g0[2 * s3]);  bH = f4add(bH, g_g0[2 * s3 + 1]);
    }
    for (; j < cnt; j++) {
        int s = g_col[st + j];
        aL = f4add(aL, g_g0[2 * s]);   aH = f4add(aH, g_g0[2 * s + 1]);
    }
    aL = f4add(aL, bL); aH = f4add(aH, bH);
    float di = g_dinv[i];
    float a[8];
    a[0] = di * aL.x; a[1] = di * aL.y; a[2] = di * aL.z; a[3] = di * aL.w;
    a[4] = di * aH.x; a[5] = di * aH.y; a[6] = di * aH.z; a[7] = di * aH.w;

    // ---- gemm1 + relu + dinv prescale, bf16 out ----
    __nv_bfloat162* out = &g_g1b[i * 32];
#pragma unroll
    for (int t4 = 0; t4 < 16; t4++) {
        float r0 = b1s[4 * t4],     r1 = b1s[4 * t4 + 1];
        float r2 = b1s[4 * t4 + 2], r3 = b1s[4 * t4 + 3];
#pragma unroll
        for (int k = 0; k < 8; k++) {
            float ak = a[k];
            const float* wr = &W1s[k * 64 + 4 * t4];
            r0 += ak * wr[0]; r1 += ak * wr[1];
            r2 += ak * wr[2]; r3 += ak * wr[3];
        }
        float2 p0 = make_float2(di * fmaxf(r0, 0.0f), di * fmaxf(r1, 0.0f));
        float2 p1 = make_float2(di * fmaxf(r2, 0.0f), di * fmaxf(r3, 0.0f));
        out[2 * t4]     = __float22bfloat162_rn(p0);
        out[2 * t4 + 1] = __float22bfloat162_rn(p1);
    }
}

// ---------------------------------------------------------------------------
// agg2: warp per node; a2[d] = dinv[d]*(sum g1[src] + g1[d]), 64 feats (bf16 in)
__global__ void k_agg2(int n) {
    int gtid = blockIdx.x * blockDim.x + threadIdx.x;
    int node = gtid >> 5;
    int lane = gtid & 31;
    if (node >= n) return;
    float2 acc = __bfloat1622float2(g_g1b[node * 32 + lane]);   // self loop
    int st = g_row_start[node];
    int cnt = g_deg[node] - 1;
    for (int base = 0; base < cnt; base += 32) {
        int idx = base + lane;
        int s = (idx < cnt) ? g_col[st + idx] : 0;
        int m = cnt - base; if (m > 32) m = 32;
        for (int j = 0; j < m; j++) {
            int sj = __shfl_sync(0xffffffffu, s, j);
            float2 v = __bfloat1622float2(g_g1b[sj * 32 + lane]); // 128B/row coalesced
            acc.x += v.x; acc.y += v.y;
        }
    }
    float di = g_dinv[node];
    ((float2*)g_a2)[node * 32 + lane] = make_float2(di * acc.x, di * acc.y);
}

// ---------------------------------------------------------------------------
// gemm2 + relu + Wfc dot + block reduction (packed fp32 fma.rn.f32x2)
__global__ void __launch_bounds__(256)
k_gemm2_reduce(const float* __restrict__ W2, const float* __restrict__ b2,
               const float* __restrict__ Wfc, int n) {
    __shared__ float W2s[64 * 128];
    __shared__ float b2s[128];
    __shared__ float wfs[128];
    __shared__ float red[256];
    int tid = threadIdx.x;
    for (int t = tid; t < 2048; t += blockDim.x)
        ((float4*)W2s)[t] = ((const float4*)W2)[t];
    if (tid < 128) { b2s[tid] = b2[tid]; wfs[tid] = Wfc[tid]; }
    __syncthreads();

    int i = blockIdx.x * blockDim.x + tid;
    float nodesum = 0.0f;
    if (i < n) {
        float a[64];
        const float4* ar = &g_a2[i * 16];
#pragma unroll
        for (int t = 0; t < 16; t++) {
            float4 v = ar[t];
            a[4 * t] = v.x; a[4 * t + 1] = v.y; a[4 * t + 2] = v.z; a[4 * t + 3] = v.w;
        }
        for (int ch = 0; ch < 4; ch++) {
            unsigned long long acc[16];
#pragma unroll
            for (int t = 0; t < 16; t++) acc[t] = 0ull;
#pragma unroll
            for (int k = 0; k < 64; k++) {
                unsigned int au = __float_as_uint(a[k]);
                unsigned long long ap;
                asm("mov.b64 %0, {%1, %1};" : "=l"(ap) : "r"(au));
                const ulonglong2* w =
                    reinterpret_cast<const ulonglong2*>(&W2s[k * 128 + ch * 32]);
#pragma unroll
                for (int t = 0; t < 8; t++) {
                    ulonglong2 wv = w[t];
                    asm("fma.rn.f32x2 %0, %1, %2, %0;"
                        : "+l"(acc[2 * t]) : "l"(ap), "l"(wv.x));
                    asm("fma.rn.f32x2 %0, %1, %2, %0;"
                        : "+l"(acc[2 * t + 1]) : "l"(ap), "l"(wv.y));
                }
            }
#pragma unroll
            for (int u = 0; u < 16; u++) {
                unsigned int lo_u, hi_u;
                asm("mov.b64 {%0, %1}, %2;" : "=r"(lo_u), "=r"(hi_u) : "l"(acc[u]));
                int c = ch * 32 + 2 * u;
                float v0 = fmaxf(__uint_as_float(lo_u) + b2s[c], 0.0f);
                float v1 = fmaxf(__uint_as_float(hi_u) + b2s[c + 1], 0.0f);
                nodesum += v0 * wfs[c] + v1 * wfs[c + 1];
            }
        }
    }
    red[tid] = nodesum;
    __syncthreads();
    for (int off = 128; off > 0; off >>= 1) {
        if (tid < off) red[tid] += red[tid + off];
        __syncthreads();
    }
    if (tid == 0) atomicAdd(&g_total, red[0]);
}

__global__ void k_final(const float* __restrict__ bfc, float* __restrict__ out, float invn) {
    out[0] = g_total * invn + bfc[0];
}

// ---------------------------------------------------------------------------
extern "C" void kernel_launch(void* const* d_in, const int* in_sizes, int n_in,
                              void* d_out, int out_size) {
    const float* x   = (const float*)d_in[0];
    const int*   ei  = (const int*)  d_in[1];
    const float* W1  = (const float*)d_in[2];
    const float* b1  = (const float*)d_in[3];
    const float* W2  = (const float*)d_in[4];
    const float* b2  = (const float*)d_in[5];
    const float* Wfc = (const float*)d_in[6];
    const float* bfc = (const float*)d_in[7];

    int n = in_sizes[0] / 8;
    int E = in_sizes[1] / 2;
    if (n > N_MAX) n = N_MAX;
    if (E > E_MAX) E = E_MAX;

    int nb = (n + 255) / 256;
    int eb = (E + 255) / 256;
    int sb = (n + 1023) / 1024;
    int wb = (n * 32 + 255) / 256;

    k_init        <<<nb, 256>>>(n);
    k_hist        <<<eb, 256>>>(ei, E);
    k_scan_dinv_g0<<<sb, 1024>>>(x, n);
    k_scatter     <<<eb, 256>>>(ei, E);
    k_agg1_gemm1  <<<nb, 256>>>(W1, b1, n);
    k_agg2        <<<wb, 256>>>(n);
    k_gemm2_reduce<<<nb, 256>>>(W2, b2, Wfc, n);
    k_final       <<<1, 1>>>(bfc, (float*)d_out, 1.0f / (float)n);
}

// round 4
// speedup vs baseline: 1.0233x; 1.0126x over previous
#include <cuda_runtime.h>
#include <cuda_bf16.h>
#include <cstdint>

// ---------------------------------------------------------------------------
// StressGNN: 2-layer GCN + mean readout + FC.
//   deg/dinv -> CSR (rank recorded in hist; atomic-free scatter) ->
//   [agg1+gemm1 fused] -> agg2 (ILP gather, bf16 in / fp32 out) ->
//   [gemm2(FFMA2 packed fp32) + relu + Wfc-dot + mean-reduce fused]
// NOTE: tcgen05 is NOT available — harness lowers PTX to .target sm_103
// (no 'a' feature set). Tensor pipe unreachable; fma pipe is the GEMM ceiling.
// ---------------------------------------------------------------------------

#define N_MAX 100000
#define E_MAX 1600000

__device__ int    g_deg[N_MAX];              // in-degree + 1 (self loop)
__device__ int    g_row_start[N_MAX];        // CSR row starts
__device__ int    g_rank[E_MAX];             // edge rank within dst bucket
__device__ int    g_col[E_MAX];              // src grouped by dst
__device__ float  g_dinv[N_MAX];             // deg^-1/2
__device__ float4 g_g0[2 * N_MAX];           // dinv[i]*x[i]             [N,8]
__device__ __nv_bfloat162 g_g1b[32 * N_MAX]; // dinv[i]*relu(a1@W1+b1)   [N,64] bf16
__device__ float4 g_a2[16 * N_MAX];          // layer-2 aggregated input [N,64]
__device__ int    g_counter;
__device__ float  g_total;

__device__ __forceinline__ float4 f4add(float4 a, float4 b) {
    return make_float4(a.x + b.x, a.y + b.y, a.z + b.z, a.w + b.w);
}
__device__ __forceinline__ float4 f4scale(float s, float4 a) {
    return make_float4(s * a.x, s * a.y, s * a.z, s * a.w);
}

// ---------------------------------------------------------------------------
__global__ void k_init(int n) {
    int i = blockIdx.x * blockDim.x + threadIdx.x;
    if (i < n) g_deg[i] = 1;  // self loop
    if (i == 0) { g_counter = 0; g_total = 0.0f; }
}

// histogram + record each edge's rank within its bucket (coalesced store)
__global__ void k_hist(const int* __restrict__ ei, int E) {
    int e = blockIdx.x * blockDim.x + threadIdx.x;
    if (e >= E) return;
    int d = ei[E + e];
    int pos = atomicAdd(&g_deg[d], 1);   // deg starts at 1
    g_rank[e] = pos - 1;
}

// block scan + atomic base -> CSR row starts; also dinv + g0
__global__ void k_scan_dinv_g0(const float* __restrict__ x, int n) {
    __shared__ int sh[1024];
    __shared__ int s_base;
    int tid = threadIdx.x;
    int i = blockIdx.x * 1024 + tid;
    int deg = (i < n) ? g_deg[i] : 1;
    int c = deg - 1;
    sh[tid] = c;
    __syncthreads();
    for (int off = 1; off < 1024; off <<= 1) {
        int v = (tid >= off) ? sh[tid - off] : 0;
        __syncthreads();
        sh[tid] += v;
        __syncthreads();
    }
    if (tid == 0) s_base = atomicAdd(&g_counter, sh[1023]);
    __syncthreads();
    int rs = s_base + sh[tid] - c;
    if (i < n) {
        g_row_start[i] = rs;
        float di = rsqrtf((float)deg);
        g_dinv[i] = di;
        const float4* x4 = (const float4*)x;
        g_g0[2 * i]     = f4scale(di, x4[2 * i]);
        g_g0[2 * i + 1] = f4scale(di, x4[2 * i + 1]);
    }
}

// atomic-free scatter: position = row_start[dst] + rank[e]
__global__ void k_scatter(const int* __restrict__ ei, int E) {
    int e = blockIdx.x * blockDim.x + threadIdx.x;
    if (e >= E) return;
    int s = ei[e];
    int d = ei[E + e];
    g_col[g_row_start[d] + g_rank[e]] = s;
}

// ---------------------------------------------------------------------------
// Fused layer 1: a1 = dinv*(sum g0[src] + g0[self]); g1 = bf16(dinv*relu(a1@W1+b1))
__global__ void __launch_bounds__(256)
k_agg1_gemm1(const float* __restrict__ W1, const float* __restrict__ b1, int n) {
    __shared__ float W1s[8 * 64];
    __shared__ float b1s[64];
    int tid = threadIdx.x;
    for (int t = tid; t < 512; t += blockDim.x) W1s[t] = W1[t];
    if (tid < 64) b1s[tid] = b1[tid];
    __syncthreads();

    int i = blockIdx.x * blockDim.x + tid;
    if (i >= n) return;

    float4 aL = g_g0[2 * i];
    float4 aH = g_g0[2 * i + 1];
    float4 bL = make_float4(0, 0, 0, 0);
    float4 bH = make_float4(0, 0, 0, 0);
    int st = g_row_start[i];
    int cnt = g_deg[i] - 1;
    int j = 0;
    for (; j + 4 <= cnt; j += 4) {
        int s0 = g_col[st + j], s1 = g_col[st + j + 1];
        int s2 = g_col[st + j + 2], s3 = g_col[st + j + 3];
        aL = f4add(aL, g_g0[2 * s0]);  aH = f4add(aH, g_g0[2 * s0 + 1]);
        bL = f4add(bL, g_g0[2 * s1]);  bH = f4add(bH, g_g0[2 * s1 + 1]);
        aL = f4add(aL, g_g0[2 * s2]);  aH = f4add(aH, g_g0[2 * s2 + 1]);
        bL = f4add(bL, g_g0[2 * s3]);  bH = f4add(bH, g_g0[2 * s3 + 1]);
    }
    for (; j < cnt; j++) {
        int s = g_col[st + j];
        aL = f4add(aL, g_g0[2 * s]);   aH = f4add(aH, g_g0[2 * s + 1]);
    }
    aL = f4add(aL, bL); aH = f4add(aH, bH);
    float di = g_dinv[i];
    float a[8];
    a[0] = di * aL.x; a[1] = di * aL.y; a[2] = di * aL.z; a[3] = di * aL.w;
    a[4] = di * aH.x; a[5] = di * aH.y; a[6] = di * aH.z; a[7] = di * aH.w;

    __nv_bfloat162* out = &g_g1b[i * 32];
#pragma unroll
    for (int t4 = 0; t4 < 16; t4++) {
        float r0 = b1s[4 * t4],     r1 = b1s[4 * t4 + 1];
        float r2 = b1s[4 * t4 + 2], r3 = b1s[4 * t4 + 3];
#pragma unroll
        for (int k = 0; k < 8; k++) {
            float ak = a[k];
            const float* wr = &W1s[k * 64 + 4 * t4];
            r0 += ak * wr[0]; r1 += ak * wr[1];
            r2 += ak * wr[2]; r3 += ak * wr[3];
        }
        out[2 * t4]     = __float22bfloat162_rn(make_float2(di * fmaxf(r0, 0.f), di * fmaxf(r1, 0.f)));
        out[2 * t4 + 1] = __float22bfloat162_rn(make_float2(di * fmaxf(r2, 0.f), di * fmaxf(r3, 0.f)));
    }
}

// ---------------------------------------------------------------------------
// agg2: warp/node. Uniform index loads (L1 broadcast, no shfl chain),
// 4-way unroll with 2 independent accumulators -> MLP>=4 per lane.
__global__ void k_agg2(int n) {
    int gtid = blockIdx.x * blockDim.x + threadIdx.x;
    int node = gtid >> 5;
    int lane = gtid & 31;
    if (node >= n) return;
    float2 acc0 = __bfloat1622float2(g_g1b[node * 32 + lane]);   // self loop
    float2 acc1 = make_float2(0.f, 0.f);
    int st = g_row_start[node];
    int cnt = g_deg[node] - 1;
    const int* col = &g_col[st];
    int j = 0;
    for (; j + 4 <= cnt; j += 4) {
        int s0 = col[j], s1 = col[j + 1], s2 = col[j + 2], s3 = col[j + 3];
        float2 v0 = __bfloat1622float2(g_g1b[s0 * 32 + lane]);
        float2 v1 = __bfloat1622float2(g_g1b[s1 * 32 + lane]);
        float2 v2 = __bfloat1622float2(g_g1b[s2 * 32 + lane]);
        float2 v3 = __bfloat1622float2(g_g1b[s3 * 32 + lane]);
        acc0.x += v0.x; acc0.y += v0.y;
        acc1.x += v1.x; acc1.y += v1.y;
        acc0.x += v2.x; acc0.y += v2.y;
        acc1.x += v3.x; acc1.y += v3.y;
    }
    for (; j < cnt; j++) {
        int s = col[j];
        float2 v = __bfloat1622float2(g_g1b[s * 32 + lane]);
        acc0.x += v.x; acc0.y += v.y;
    }
    float di = g_dinv[node];
    ((float2*)g_a2)[node * 32 + lane] =
        make_float2(di * (acc0.x + acc1.x), di * (acc0.y + acc1.y));
}

// ---------------------------------------------------------------------------
// gemm2 + relu + Wfc dot + block reduction (packed fp32 fma.rn.f32x2)
__global__ void __launch_bounds__(256)
k_gemm2_reduce(const float* __restrict__ W2, const float* __restrict__ b2,
               const float* __restrict__ Wfc, int n) {
    __shared__ float W2s[64 * 128];
    __shared__ float b2s[128];
    __shared__ float wfs[128];
    __shared__ float red[256];
    int tid = threadIdx.x;
    for (int t = tid; t < 2048; t += blockDim.x)
        ((float4*)W2s)[t] = ((const float4*)W2)[t];
    if (tid < 128) { b2s[tid] = b2[tid]; wfs[tid] = Wfc[tid]; }
    __syncthreads();

    int i = blockIdx.x * blockDim.x + tid;
    float nodesum = 0.0f;
    if (i < n) {
        float a[64];
        const float4* ar = &g_a2[i * 16];
#pragma unroll
        for (int t = 0; t < 16; t++) {
            float4 v = ar[t];
            a[4 * t] = v.x; a[4 * t + 1] = v.y; a[4 * t + 2] = v.z; a[4 * t + 3] = v.w;
        }
        for (int ch = 0; ch < 4; ch++) {
            unsigned long long acc[16];
#pragma unroll
            for (int t = 0; t < 16; t++) acc[t] = 0ull;
#pragma unroll
            for (int k = 0; k < 64; k++) {
                unsigned int au = __float_as_uint(a[k]);
                unsigned long long ap;
                asm("mov.b64 %0, {%1, %1};" : "=l"(ap) : "r"(au));
                const ulonglong2* w =
                    reinterpret_cast<const ulonglong2*>(&W2s[k * 128 + ch * 32]);
#pragma unroll
                for (int t = 0; t < 8; t++) {
                    ulonglong2 wv = w[t];
                    asm("fma.rn.f32x2 %0, %1, %2, %0;"
                        : "+l"(acc[2 * t]) : "l"(ap), "l"(wv.x));
                    asm("fma.rn.f32x2 %0, %1, %2, %0;"
                        : "+l"(acc[2 * t + 1]) : "l"(ap), "l"(wv.y));
                }
            }
#pragma unroll
            for (int u = 0; u < 16; u++) {
                unsigned int lo_u, hi_u;
                asm("mov.b64 {%0, %1}, %2;" : "=r"(lo_u), "=r"(hi_u) : "l"(acc[u]));
                int c = ch * 32 + 2 * u;
                float v0 = fmaxf(__uint_as_float(lo_u) + b2s[c], 0.0f);
                float v1 = fmaxf(__uint_as_float(hi_u) + b2s[c + 1], 0.0f);
                nodesum += v0 * wfs[c] + v1 * wfs[c + 1];
            }
        }
    }
    red[tid] = nodesum;
    __syncthreads();
    for (int off = 128; off > 0; off >>= 1) {
        if (tid < off) red[tid] += red[tid + off];
        __syncthreads();
    }
    if (tid == 0) atomicAdd(&g_total, red[0]);
}

__global__ void k_final(const float* __restrict__ bfc, float* __restrict__ out, float invn) {
    out[0] = g_total * invn + bfc[0];
}

// ---------------------------------------------------------------------------
extern "C" void kernel_launch(void* const* d_in, const int* in_sizes, int n_in,
                              void* d_out, int out_size) {
    const float* x   = (const float*)d_in[0];
    const int*   ei  = (const int*)  d_in[1];
    const float* W1  = (const float*)d_in[2];
    const float* b1  = (const float*)d_in[3];
    const float* W2  = (const float*)d_in[4];
    const float* b2  = (const float*)d_in[5];
    const float* Wfc = (const float*)d_in[6];
    const float* bfc = (const float*)d_in[7];

    int n = in_sizes[0] / 8;
    int E = in_sizes[1] / 2;
    if (n > N_MAX) n = N_MAX;
    if (E > E_MAX) E = E_MAX;

    int nb = (n + 255) / 256;
    int eb = (E + 255) / 256;
    int sb = (n + 1023) / 1024;
    int wb = (n * 32 + 255) / 256;

    k_init        <<<nb, 256>>>(n);
    k_hist        <<<eb, 256>>>(ei, E);
    k_scan_dinv_g0<<<sb, 1024>>>(x, n);
    k_scatter     <<<eb, 256>>>(ei, E);
    k_agg1_gemm1  <<<nb, 256>>>(W1, b1, n);
    k_agg2        <<<wb, 256>>>(n);
    k_gemm2_reduce<<<nb, 256>>>(W2, b2, Wfc, n);
    k_final       <<<1, 1>>>(bfc, (float*)d_out, 1.0f / (float)n);
}

// round 5
// speedup vs baseline: 1.0316x; 1.0080x over previous
#include <cuda_runtime.h>
#include <cuda_bf16.h>
#include <cstdint>

// ---------------------------------------------------------------------------
// StressGNN: 2-layer GCN + mean readout + FC.
//   hist(deg+rank) -> scan(row_start,cnt,dinv,g0; deg self-reset) ->
//   scatter (atomic-free) -> [agg1+gemm1 fused] -> agg2 (MLP-8 gather) ->
//   [gemm2(FFMA2) + relu + Wfc-dot + mean-reduce] -> final (total self-reset)
// State is self-resetting: __device__ globals start zeroed; each replay
// leaves deg/counter/total zeroed again => graph-replay deterministic.
// tcgen05 unavailable (harness lowers to .target sm_103, no 'a').
// ---------------------------------------------------------------------------

#define N_MAX 100000
#define E_MAX 1600000

__device__ int    g_deg[N_MAX];              // edge count (zeroed each cycle)
__device__ int    g_cnt[N_MAX];              // snapshot: in-edges per node
__device__ int    g_row_start[N_MAX];        // CSR row starts
__device__ int    g_rank[E_MAX];             // edge rank within dst bucket
__device__ int    g_col[E_MAX];              // src grouped by dst
__device__ float  g_dinv[N_MAX];             // (cnt+1)^-1/2
__device__ float4 g_g0[2 * N_MAX];           // dinv[i]*x[i]             [N,8]
__device__ __nv_bfloat162 g_g1b[32 * N_MAX]; // dinv[i]*relu(a1@W1+b1)   [N,64] bf16
__device__ float4 g_a2[16 * N_MAX];          // layer-2 aggregated input [N,64]
__device__ int    g_counter;
__device__ float  g_total;

__device__ __forceinline__ float4 f4add(float4 a, float4 b) {
    return make_float4(a.x + b.x, a.y + b.y, a.z + b.z, a.w + b.w);
}
__device__ __forceinline__ float4 f4scale(float s, float4 a) {
    return make_float4(s * a.x, s * a.y, s * a.z, s * a.w);
}

// ---------------------------------------------------------------------------
// histogram + record each edge's rank within its bucket (coalesced store)
__global__ void k_hist(const int* __restrict__ ei, int E) {
    int e = blockIdx.x * blockDim.x + threadIdx.x;
    if (e >= E) return;
    int d = ei[E + e];
    g_rank[e] = atomicAdd(&g_deg[d], 1);   // deg starts at 0 every replay
}

// block scan + atomic base -> CSR row starts; snapshot cnt; reset deg; dinv+g0
__global__ void k_scan_dinv_g0(const float* __restrict__ x, int n) {
    __shared__ int sh[1024];
    __shared__ int s_base;
    int tid = threadIdx.x;
    int i = blockIdx.x * 1024 + tid;
    int c = (i < n) ? g_deg[i] : 0;
    sh[tid] = c;
    __syncthreads();
    for (int off = 1; off < 1024; off <<= 1) {
        int v = (tid >= off) ? sh[tid - off] : 0;
        __syncthreads();
        sh[tid] += v;
        __syncthreads();
    }
    if (tid == 0) s_base = atomicAdd(&g_counter, sh[1023]);
    __syncthreads();
    int rs = s_base + sh[tid] - c;
    if (i < n) {
        g_row_start[i] = rs;
        g_cnt[i] = c;
        g_deg[i] = 0;                       // self-reset for next replay
        float di = rsqrtf((float)(c + 1));  // +1 self loop
        g_dinv[i] = di;
        const float4* x4 = (const float4*)x;
        g_g0[2 * i]     = f4scale(di, x4[2 * i]);
        g_g0[2 * i + 1] = f4scale(di, x4[2 * i + 1]);
    }
}

// atomic-free scatter: position = row_start[dst] + rank[e]; resets counter
__global__ void k_scatter(const int* __restrict__ ei, int E) {
    int e = blockIdx.x * blockDim.x + threadIdx.x;
    if (e == 0) g_counter = 0;              // self-reset for next replay
    if (e >= E) return;
    int s = ei[e];
    int d = ei[E + e];
    g_col[g_row_start[d] + g_rank[e]] = s;
}

// ---------------------------------------------------------------------------
// Fused layer 1: a1 = dinv*(sum g0[src] + g0[self]); g1 = bf16(dinv*relu(a1@W1+b1))
__global__ void __launch_bounds__(256)
k_agg1_gemm1(const float* __restrict__ W1, const float* __restrict__ b1, int n) {
    __shared__ float W1s[8 * 64];
    __shared__ float b1s[64];
    int tid = threadIdx.x;
    for (int t = tid; t < 512; t += blockDim.x) W1s[t] = W1[t];
    if (tid < 64) b1s[tid] = b1[tid];
    __syncthreads();

    int i = blockIdx.x * blockDim.x + tid;
    if (i >= n) return;

    float4 aL = g_g0[2 * i];
    float4 aH = g_g0[2 * i + 1];
    float4 bL = make_float4(0, 0, 0, 0);
    float4 bH = make_float4(0, 0, 0, 0);
    int st = g_row_start[i];
    int cnt = g_cnt[i];
    int j = 0;
    for (; j + 4 <= cnt; j += 4) {
        int s0 = g_col[st + j], s1 = g_col[st + j + 1];
        int s2 = g_col[st + j + 2], s3 = g_col[st + j + 3];
        aL = f4add(aL, g_g0[2 * s0]);  aH = f4add(aH, g_g0[2 * s0 + 1]);
        bL = f4add(bL, g_g0[2 * s1]);  bH = f4add(bH, g_g0[2 * s1 + 1]);
        aL = f4add(aL, g_g0[2 * s2]);  aH = f4add(aH, g_g0[2 * s2 + 1]);
        bL = f4add(bL, g_g0[2 * s3]);  bH = f4add(bH, g_g0[2 * s3 + 1]);
    }
    for (; j < cnt; j++) {
        int s = g_col[st + j];
        aL = f4add(aL, g_g0[2 * s]);   aH = f4add(aH, g_g0[2 * s + 1]);
    }
    aL = f4add(aL, bL); aH = f4add(aH, bH);
    float di = g_dinv[i];
    float a[8];
    a[0] = di * aL.x; a[1] = di * aL.y; a[2] = di * aL.z; a[3] = di * aL.w;
    a[4] = di * aH.x; a[5] = di * aH.y; a[6] = di * aH.z; a[7] = di * aH.w;

    __nv_bfloat162* out = &g_g1b[i * 32];
#pragma unroll
    for (int t4 = 0; t4 < 16; t4++) {
        float r0 = b1s[4 * t4],     r1 = b1s[4 * t4 + 1];
        float r2 = b1s[4 * t4 + 2], r3 = b1s[4 * t4 + 3];
#pragma unroll
        for (int k = 0; k < 8; k++) {
            float ak = a[k];
            const float* wr = &W1s[k * 64 + 4 * t4];
            r0 += ak * wr[0]; r1 += ak * wr[1];
            r2 += ak * wr[2]; r3 += ak * wr[3];
        }
        out[2 * t4]     = __float22bfloat162_rn(make_float2(di * fmaxf(r0, 0.f), di * fmaxf(r1, 0.f)));
        out[2 * t4 + 1] = __float22bfloat162_rn(make_float2(di * fmaxf(r2, 0.f), di * fmaxf(r3, 0.f)));
    }
}

// ---------------------------------------------------------------------------
// agg2: warp/node, unroll 8 with 4 independent accumulator chains (MLP~8).
__global__ void k_agg2(int n) {
    int gtid = blockIdx.x * blockDim.x + threadIdx.x;
    int node = gtid >> 5;
    int lane = gtid & 31;
    if (node >= n) return;
    float2 acc0 = __bfloat1622float2(g_g1b[node * 32 + lane]);   // self loop
    float2 acc1 = make_float2(0.f, 0.f);
    float2 acc2 = make_float2(0.f, 0.f);
    float2 acc3 = make_float2(0.f, 0.f);
    int st = g_row_start[node];
    int cnt = g_cnt[node];
    const int* col = &g_col[st];
    int j = 0;
    for (; j + 8 <= cnt; j += 8) {
        int s0 = col[j],     s1 = col[j + 1], s2 = col[j + 2], s3 = col[j + 3];
        int s4 = col[j + 4], s5 = col[j + 5], s6 = col[j + 6], s7 = col[j + 7];
        float2 v0 = __bfloat1622float2(g_g1b[s0 * 32 + lane]);
        float2 v1 = __bfloat1622float2(g_g1b[s1 * 32 + lane]);
        float2 v2 = __bfloat1622float2(g_g1b[s2 * 32 + lane]);
        float2 v3 = __bfloat1622float2(g_g1b[s3 * 32 + lane]);
        float2 v4 = __bfloat1622float2(g_g1b[s4 * 32 + lane]);
        float2 v5 = __bfloat1622float2(g_g1b[s5 * 32 + lane]);
        float2 v6 = __bfloat1622float2(g_g1b[s6 * 32 + lane]);
        float2 v7 = __bfloat1622float2(g_g1b[s7 * 32 + lane]);
        acc0.x += v0.x; acc0.y += v0.y;  acc1.x += v1.x; acc1.y += v1.y;
        acc2.x += v2.x; acc2.y += v2.y;  acc3.x += v3.x; acc3.y += v3.y;
        acc0.x += v4.x; acc0.y += v4.y;  acc1.x += v5.x; acc1.y += v5.y;
        acc2.x += v6.x; acc2.y += v6.y;  acc3.x += v7.x; acc3.y += v7.y;
    }
    if (j + 4 <= cnt) {
        int s0 = col[j], s1 = col[j + 1], s2 = col[j + 2], s3 = col[j + 3];
        float2 v0 = __bfloat1622float2(g_g1b[s0 * 32 + lane]);
        float2 v1 = __bfloat1622float2(g_g1b[s1 * 32 + lane]);
        float2 v2 = __bfloat1622float2(g_g1b[s2 * 32 + lane]);
        float2 v3 = __bfloat1622float2(g_g1b[s3 * 32 + lane]);
        acc0.x += v0.x; acc0.y += v0.y;  acc1.x += v1.x; acc1.y += v1.y;
        acc2.x += v2.x; acc2.y += v2.y;  acc3.x += v3.x; acc3.y += v3.y;
        j += 4;
    }
    for (; j < cnt; j++) {
        int s = col[j];
        float2 v = __bfloat1622float2(g_g1b[s * 32 + lane]);
        acc0.x += v.x; acc0.y += v.y;
    }
    float di = g_dinv[node];
    ((float2*)g_a2)[node * 32 + lane] =
        make_float2(di * (acc0.x + acc1.x + acc2.x + acc3.x),
                    di * (acc0.y + acc1.y + acc2.y + acc3.y));
}

// ---------------------------------------------------------------------------
// gemm2 + relu + Wfc dot + block reduction (packed fp32 fma.rn.f32x2)
__global__ void __launch_bounds__(256)
k_gemm2_reduce(const float* __restrict__ W2, const float* __restrict__ b2,
               const float* __restrict__ Wfc, int n) {
    __shared__ float W2s[64 * 128];
    __shared__ float b2s[128];
    __shared__ float wfs[128];
    __shared__ float red[256];
    int tid = threadIdx.x;
    for (int t = tid; t < 2048; t += blockDim.x)
        ((float4*)W2s)[t] = ((const float4*)W2)[t];
    if (tid < 128) { b2s[tid] = b2[tid]; wfs[tid] = Wfc[tid]; }
    __syncthreads();

    int i = blockIdx.x * blockDim.x + tid;
    float nodesum = 0.0f;
    if (i < n) {
        float a[64];
        const float4* ar = &g_a2[i * 16];
#pragma unroll
        for (int t = 0; t < 16; t++) {
            float4 v = ar[t];
            a[4 * t] = v.x; a[4 * t + 1] = v.y; a[4 * t + 2] = v.z; a[4 * t + 3] = v.w;
        }
        for (int ch = 0; ch < 4; ch++) {
            unsigned long long acc[16];
#pragma unroll
            for (int t = 0; t < 16; t++) acc[t] = 0ull;
#pragma unroll
            for (int k = 0; k < 64; k++) {
                unsigned int au = __float_as_uint(a[k]);
                unsigned long long ap;
                asm("mov.b64 %0, {%1, %1};" : "=l"(ap) : "r"(au));
                const ulonglong2* w =
                    reinterpret_cast<const ulonglong2*>(&W2s[k * 128 + ch * 32]);
#pragma unroll
                for (int t = 0; t < 8; t++) {
                    ulonglong2 wv = w[t];
                    asm("fma.rn.f32x2 %0, %1, %2, %0;"
                        : "+l"(acc[2 * t]) : "l"(ap), "l"(wv.x));
                    asm("fma.rn.f32x2 %0, %1, %2, %0;"
                        : "+l"(acc[2 * t + 1]) : "l"(ap), "l"(wv.y));
                }
            }
#pragma unroll
            for (int u = 0; u < 16; u++) {
                unsigned int lo_u, hi_u;
                asm("mov.b64 {%0, %1}, %2;" : "=r"(lo_u), "=r"(hi_u) : "l"(acc[u]));
                int c = ch * 32 + 2 * u;
                float v0 = fmaxf(__uint_as_float(lo_u) + b2s[c], 0.0f);
                float v1 = fmaxf(__uint_as_float(hi_u) + b2s[c + 1], 0.0f);
                nodesum += v0 * wfs[c] + v1 * wfs[c + 1];
            }
        }
    }
    red[tid] = nodesum;
    __syncthreads();
    for (int off = 128; off > 0; off >>= 1) {
        if (tid < off) red[tid] += red[tid + off];
        __syncthreads();
    }
    if (tid == 0) atomicAdd(&g_total, red[0]);
}

__global__ void k_final(const float* __restrict__ bfc, float* __restrict__ out, float invn) {
    out[0] = g_total * invn + bfc[0];
    g_total = 0.0f;                          // self-reset for next replay
}

// ---------------------------------------------------------------------------
extern "C" void kernel_launch(void* const* d_in, const int* in_sizes, int n_in,
                              void* d_out, int out_size) {
    const float* x   = (const float*)d_in[0];
    const int*   ei  = (const int*)  d_in[1];
    const float* W1  = (const float*)d_in[2];
    const float* b1  = (const float*)d_in[3];
    const float* W2  = (const float*)d_in[4];
    const float* b2  = (const float*)d_in[5];
    const float* Wfc = (const float*)d_in[6];
    const float* bfc = (const float*)d_in[7];

    int n = in_sizes[0] / 8;
    int E = in_sizes[1] / 2;
    if (n > N_MAX) n = N_MAX;
    if (E > E_MAX) E = E_MAX;

    int nb = (n + 255) / 256;
    int eb = (E + 255) / 256;
    int sb = (n + 1023) / 1024;
    int wb = (n * 32 + 255) / 256;

    k_hist        <<<eb, 256>>>(ei, E);
    k_scan_dinv_g0<<<sb, 1024>>>(x, n);
    k_scatter     <<<eb, 256>>>(ei, E);
    k_agg1_gemm1  <<<nb, 256>>>(W1, b1, n);
    k_agg2        <<<wb, 256>>>(n);
    k_gemm2_reduce<<<nb, 256>>>(W2, b2, Wfc, n);
    k_final       <<<1, 1>>>(bfc, (float*)d_out, 1.0f / (float)n);
}

// round 6
// speedup vs baseline: 1.0656x; 1.0330x over previous
#include <cuda_runtime.h>
#include <cuda_bf16.h>
#include <cstdint>

// ---------------------------------------------------------------------------
// StressGNN: 2-layer GCN + mean readout + FC.
//   hist(deg+rank) -> scan(row_start,cnt,dinv,g0; deg self-reset) ->
//   scatter (atomic-free) -> [agg1+gemm1 fused, 4 lanes/node] ->
//   agg2 (warp/node MLP-8) -> [gemm2(FFMA2) + relu + Wfc-dot + reduce] -> final
// Self-resetting device state => graph-replay deterministic.
// tcgen05 unavailable (harness lowers to .target sm_103, no 'a').
// ---------------------------------------------------------------------------

#define N_MAX 100000
#define E_MAX 1600000

__device__ int    g_deg[N_MAX];              // edge count (zeroed each cycle)
__device__ int    g_cnt[N_MAX];              // snapshot: in-edges per node
__device__ int    g_row_start[N_MAX];        // CSR row starts
__device__ int    g_rank[E_MAX];             // edge rank within dst bucket
__device__ int    g_col[E_MAX];              // src grouped by dst
__device__ float  g_dinv[N_MAX];             // (cnt+1)^-1/2
__device__ float2 g_g0[4 * N_MAX];           // dinv[i]*x[i]             [N,8]
__device__ __nv_bfloat162 g_g1b[32 * N_MAX]; // dinv[i]*relu(a1@W1+b1)   [N,64] bf16
__device__ float4 g_a2[16 * N_MAX];          // layer-2 aggregated input [N,64]
__device__ int    g_counter;
__device__ float  g_total;

// ---------------------------------------------------------------------------
// histogram + record each edge's rank within its bucket (coalesced store)
__global__ void k_hist(const int* __restrict__ ei, int E) {
    int e = blockIdx.x * blockDim.x + threadIdx.x;
    if (e >= E) return;
    int d = ei[E + e];
    g_rank[e] = atomicAdd(&g_deg[d], 1);   // deg starts at 0 every replay
}

// block scan + atomic base -> CSR row starts; snapshot cnt; reset deg; dinv+g0
__global__ void k_scan_dinv_g0(const float* __restrict__ x, int n) {
    __shared__ int sh[1024];
    __shared__ int s_base;
    int tid = threadIdx.x;
    int i = blockIdx.x * 1024 + tid;
    int c = (i < n) ? g_deg[i] : 0;
    sh[tid] = c;
    __syncthreads();
    for (int off = 1; off < 1024; off <<= 1) {
        int v = (tid >= off) ? sh[tid - off] : 0;
        __syncthreads();
        sh[tid] += v;
        __syncthreads();
    }
    if (tid == 0) s_base = atomicAdd(&g_counter, sh[1023]);
    __syncthreads();
    int rs = s_base + sh[tid] - c;
    if (i < n) {
        g_row_start[i] = rs;
        g_cnt[i] = c;
        g_deg[i] = 0;                       // self-reset for next replay
        float di = rsqrtf((float)(c + 1));  // +1 self loop
        g_dinv[i] = di;
        const float4* x4 = (const float4*)x;
        float4 v0 = x4[2 * i], v1 = x4[2 * i + 1];
        g_g0[4 * i]     = make_float2(di * v0.x, di * v0.y);
        g_g0[4 * i + 1] = make_float2(di * v0.z, di * v0.w);
        g_g0[4 * i + 2] = make_float2(di * v1.x, di * v1.y);
        g_g0[4 * i + 3] = make_float2(di * v1.z, di * v1.w);
    }
}

// atomic-free scatter: position = row_start[dst] + rank[e]; resets counter
__global__ void k_scatter(const int* __restrict__ ei, int E) {
    int e = blockIdx.x * blockDim.x + threadIdx.x;
    if (e == 0) g_counter = 0;              // self-reset for next replay
    if (e >= E) return;
    int s = ei[e];
    int d = ei[E + e];
    g_col[g_row_start[d] + g_rank[e]] = s;
}

// ---------------------------------------------------------------------------
// Fused layer 1, 4 lanes per node (4x occupancy vs thread-per-node):
//   each lane owns 2 of 8 input features during aggregation; shfl(width=4)
//   reassembles the vector; each lane emits 16 of 64 bf16 outputs.
__global__ void __launch_bounds__(256)
k_agg1_gemm1(const float* __restrict__ W1, const float* __restrict__ b1, int n) {
    __shared__ float W1s[8 * 64];
    __shared__ float b1s[64];
    int tid = threadIdx.x;
    for (int t = tid; t < 512; t += blockDim.x) W1s[t] = W1[t];
    if (tid < 64) b1s[tid] = b1[tid];
    __syncthreads();

    int gtid = blockIdx.x * blockDim.x + tid;
    int node = gtid >> 2;
    int sub  = gtid & 3;
    if (node >= n) return;

    // ---- aggregation: lane handles features [2*sub, 2*sub+1] ----
    float2 acc0 = g_g0[4 * node + sub];     // self loop
    float2 acc1 = make_float2(0.f, 0.f);
    int st = g_row_start[node];
    int cnt = g_cnt[node];
    const int* col = &g_col[st];
    int j = 0;
    for (; j + 4 <= cnt; j += 4) {
        int s0 = col[j], s1 = col[j + 1], s2 = col[j + 2], s3 = col[j + 3];
        float2 v0 = g_g0[4 * s0 + sub];
        float2 v1 = g_g0[4 * s1 + sub];
        float2 v2 = g_g0[4 * s2 + sub];
        float2 v3 = g_g0[4 * s3 + sub];
        acc0.x += v0.x; acc0.y += v0.y;
        acc1.x += v1.x; acc1.y += v1.y;
        acc0.x += v2.x; acc0.y += v2.y;
        acc1.x += v3.x; acc1.y += v3.y;
    }
    for (; j < cnt; j++) {
        int s = col[j];
        float2 v = g_g0[4 * s + sub];
        acc0.x += v.x; acc0.y += v.y;
    }
    float di = g_dinv[node];
    float mx = di * (acc0.x + acc1.x);
    float my = di * (acc0.y + acc1.y);

    // ---- reassemble full 8-vector in every lane (shfl within group of 4) ----
    float a[8];
#pragma unroll
    for (int g = 0; g < 4; g++) {
        a[2 * g]     = __shfl_sync(0xffffffffu, mx, g, 4);
        a[2 * g + 1] = __shfl_sync(0xffffffffu, my, g, 4);
    }

    // ---- gemm1: this lane computes output cols [sub*16, sub*16+16) ----
    int cbase = sub * 16;
    float r[16];
#pragma unroll
    for (int c = 0; c < 16; c++) r[c] = b1s[cbase + c];
#pragma unroll
    for (int k = 0; k < 8; k++) {
        float ak = a[k];
        const float* wr = &W1s[k * 64 + cbase];
#pragma unroll
        for (int c = 0; c < 16; c++) r[c] += ak * wr[c];
    }
    // relu + dinv prescale + bf16 pack; group of 4 lanes writes 128B row
    __nv_bfloat162 ob[8];
#pragma unroll
    for (int t = 0; t < 8; t++)
        ob[t] = __float22bfloat162_rn(make_float2(di * fmaxf(r[2 * t], 0.f),
                                                  di * fmaxf(r[2 * t + 1], 0.f)));
    uint4* dst = (uint4*)&g_g1b[node * 32 + sub * 8];
    dst[0] = *reinterpret_cast<uint4*>(&ob[0]);
    dst[1] = *reinterpret_cast<uint4*>(&ob[4]);
}

// ---------------------------------------------------------------------------
// agg2: warp/node, unroll 8 with 4 independent accumulator chains (MLP~8).
__global__ void k_agg2(int n) {
    int gtid = blockIdx.x * blockDim.x + threadIdx.x;
    int node = gtid >> 5;
    int lane = gtid & 31;
    if (node >= n) return;
    float2 acc0 = __bfloat1622float2(g_g1b[node * 32 + lane]);   // self loop
    float2 acc1 = make_float2(0.f, 0.f);
    float2 acc2 = make_float2(0.f, 0.f);
    float2 acc3 = make_float2(0.f, 0.f);
    int st = g_row_start[node];
    int cnt = g_cnt[node];
    const int* col = &g_col[st];
    int j = 0;
    for (; j + 8 <= cnt; j += 8) {
        int s0 = col[j],     s1 = col[j + 1], s2 = col[j + 2], s3 = col[j + 3];
        int s4 = col[j + 4], s5 = col[j + 5], s6 = col[j + 6], s7 = col[j + 7];
        float2 v0 = __bfloat1622float2(g_g1b[s0 * 32 + lane]);
        float2 v1 = __bfloat1622float2(g_g1b[s1 * 32 + lane]);
        float2 v2 = __bfloat1622float2(g_g1b[s2 * 32 + lane]);
        float2 v3 = __bfloat1622float2(g_g1b[s3 * 32 + lane]);
        float2 v4 = __bfloat1622float2(g_g1b[s4 * 32 + lane]);
        float2 v5 = __bfloat1622float2(g_g1b[s5 * 32 + lane]);
        float2 v6 = __bfloat1622float2(g_g1b[s6 * 32 + lane]);
        float2 v7 = __bfloat1622float2(g_g1b[s7 * 32 + lane]);
        acc0.x += v0.x; acc0.y += v0.y;  acc1.x += v1.x; acc1.y += v1.y;
        acc2.x += v2.x; acc2.y += v2.y;  acc3.x += v3.x; acc3.y += v3.y;
        acc0.x += v4.x; acc0.y += v4.y;  acc1.x += v5.x; acc1.y += v5.y;
        acc2.x += v6.x; acc2.y += v6.y;  acc3.x += v7.x; acc3.y += v7.y;
    }
    if (j + 4 <= cnt) {
        int s0 = col[j], s1 = col[j + 1], s2 = col[j + 2], s3 = col[j + 3];
        float2 v0 = __bfloat1622float2(g_g1b[s0 * 32 + lane]);
        float2 v1 = __bfloat1622float2(g_g1b[s1 * 32 + lane]);
        float2 v2 = __bfloat1622float2(g_g1b[s2 * 32 + lane]);
        float2 v3 = __bfloat1622float2(g_g1b[s3 * 32 + lane]);
        acc0.x += v0.x; acc0.y += v0.y;  acc1.x += v1.x; acc1.y += v1.y;
        acc2.x += v2.x; acc2.y += v2.y;  acc3.x += v3.x; acc3.y += v3.y;
        j += 4;
    }
    for (; j < cnt; j++) {
        int s = col[j];
        float2 v = __bfloat1622float2(g_g1b[s * 32 + lane]);
        acc0.x += v.x; acc0.y += v.y;
    }
    float di = g_dinv[node];
    ((float2*)g_a2)[node * 32 + lane] =
        make_float2(di * (acc0.x + acc1.x + acc2.x + acc3.x),
                    di * (acc0.y + acc1.y + acc2.y + acc3.y));
}

// ---------------------------------------------------------------------------
// gemm2 + relu + Wfc dot + block reduction (packed fp32 fma.rn.f32x2)
__global__ void __launch_bounds__(256)
k_gemm2_reduce(const float* __restrict__ W2, const float* __restrict__ b2,
               const float* __restrict__ Wfc, int n) {
    __shared__ float W2s[64 * 128];
    __shared__ float b2s[128];
    __shared__ float wfs[128];
    __shared__ float red[256];
    int tid = threadIdx.x;
    for (int t = tid; t < 2048; t += blockDim.x)
        ((float4*)W2s)[t] = ((const float4*)W2)[t];
    if (tid < 128) { b2s[tid] = b2[tid]; wfs[tid] = Wfc[tid]; }
    __syncthreads();

    int i = blockIdx.x * blockDim.x + tid;
    float nodesum = 0.0f;
    if (i < n) {
        float a[64];
        const float4* ar = &g_a2[i * 16];
#pragma unroll
        for (int t = 0; t < 16; t++) {
            float4 v = ar[t];
            a[4 * t] = v.x; a[4 * t + 1] = v.y; a[4 * t + 2] = v.z; a[4 * t + 3] = v.w;
        }
        for (int ch = 0; ch < 4; ch++) {
            unsigned long long acc[16];
#pragma unroll
            for (int t = 0; t < 16; t++) acc[t] = 0ull;
#pragma unroll
            for (int k = 0; k < 64; k++) {
                unsigned int au = __float_as_uint(a[k]);
                unsigned long long ap;
                asm("mov.b64 %0, {%1, %1};" : "=l"(ap) : "r"(au));
                const ulonglong2* w =
                    reinterpret_cast<const ulonglong2*>(&W2s[k * 128 + ch * 32]);
#pragma unroll
                for (int t = 0; t < 8; t++) {
                    ulonglong2 wv = w[t];
                    asm("fma.rn.f32x2 %0, %1, %2, %0;"
                        : "+l"(acc[2 * t]) : "l"(ap), "l"(wv.x));
                    asm("fma.rn.f32x2 %0, %1, %2, %0;"
                        : "+l"(acc[2 * t + 1]) : "l"(ap), "l"(wv.y));
                }
            }
#pragma unroll
            for (int u = 0; u < 16; u++) {
                unsigned int lo_u, hi_u;
                asm("mov.b64 {%0, %1}, %2;" : "=r"(lo_u), "=r"(hi_u) : "l"(acc[u]));
                int c = ch * 32 + 2 * u;
                float v0 = fmaxf(__uint_as_float(lo_u) + b2s[c], 0.0f);
                float v1 = fmaxf(__uint_as_float(hi_u) + b2s[c + 1], 0.0f);
                nodesum += v0 * wfs[c] + v1 * wfs[c + 1];
            }
        }
    }
    red[tid] = nodesum;
    __syncthreads();
    for (int off = 128; off > 0; off >>= 1) {
        if (tid < off) red[tid] += red[tid + off];
        __syncthreads();
    }
    if (tid == 0) atomicAdd(&g_total, red[0]);
}

__global__ void k_final(const float* __restrict__ bfc, float* __restrict__ out, float invn) {
    out[0] = g_total * invn + bfc[0];
    g_total = 0.0f;                          // self-reset for next replay
}

// ---------------------------------------------------------------------------
extern "C" void kernel_launch(void* const* d_in, const int* in_sizes, int n_in,
                              void* d_out, int out_size) {
    const float* x   = (const float*)d_in[0];
    const int*   ei  = (const int*)  d_in[1];
    const float* W1  = (const float*)d_in[2];
    const float* b1  = (const float*)d_in[3];
    const float* W2  = (const float*)d_in[4];
    const float* b2  = (const float*)d_in[5];
    const float* Wfc = (const float*)d_in[6];
    const float* bfc = (const float*)d_in[7];

    int n = in_sizes[0] / 8;
    int E = in_sizes[1] / 2;
    if (n > N_MAX) n = N_MAX;
    if (E > E_MAX) E = E_MAX;

    int nb  = (n + 255) / 256;
    int eb  = (E + 255) / 256;
    int sb  = (n + 1023) / 1024;
    int qb  = (n * 4 + 255) / 256;   // 4 lanes per node
    int wb  = (n * 32 + 255) / 256;  // warp per node

    k_hist        <<<eb, 256>>>(ei, E);
    k_scan_dinv_g0<<<sb, 1024>>>(x, n);
    k_scatter     <<<eb, 256>>>(ei, E);
    k_agg1_gemm1  <<<qb, 256>>>(W1, b1, n);
    k_agg2        <<<wb, 256>>>(n);
    k_gemm2_reduce<<<nb, 256>>>(W2, b2, Wfc, n);
    k_final       <<<1, 1>>>(bfc, (float*)d_out, 1.0f / (float)n);
}

// round 7
// speedup vs baseline: 1.0728x; 1.0067x over previous
#include <cuda_runtime.h>
#include <cuda_bf16.h>
#include <cstdint>

// ---------------------------------------------------------------------------
// StressGNN: 2-layer GCN + mean readout + FC.
//   hist(deg+rank) -> scan(row_start,cnt,dinv,g0; deg self-reset) ->
//   scatter (atomic-free) -> [agg1+gemm1 fused, 4 lanes/node, coop idx] ->
//   agg2 (warp/node MLP-8) -> [gemm2(FFMA2) + relu + Wfc-dot + reduce + final]
// Self-resetting device state => graph-replay deterministic.
// tcgen05 unavailable (harness lowers to .target sm_103, no 'a').
// ---------------------------------------------------------------------------

#define N_MAX 100000
#define E_MAX 1600000

__device__ int    g_deg[N_MAX];              // edge count (zeroed each cycle)
__device__ int    g_cnt[N_MAX];              // snapshot: in-edges per node
__device__ int    g_row_start[N_MAX];        // CSR row starts
__device__ int    g_rank[E_MAX];             // edge rank within dst bucket
__device__ int    g_col[E_MAX];              // src grouped by dst
__device__ float  g_dinv[N_MAX];             // (cnt+1)^-1/2
__device__ float2 g_g0[4 * N_MAX];           // dinv[i]*x[i]             [N,8]
__device__ __nv_bfloat162 g_g1b[32 * N_MAX]; // dinv[i]*relu(a1@W1+b1)   [N,64] bf16
__device__ float4 g_a2[16 * N_MAX];          // layer-2 aggregated input [N,64]
__device__ int    g_counter;
__device__ int    g_done;
__device__ float  g_total;

// ---------------------------------------------------------------------------
// histogram + record each edge's rank within its bucket (coalesced store)
__global__ void k_hist(const int* __restrict__ ei, int E) {
    int e = blockIdx.x * blockDim.x + threadIdx.x;
    if (e >= E) return;
    int d = ei[E + e];
    g_rank[e] = atomicAdd(&g_deg[d], 1);   // deg starts at 0 every replay
}

// block scan + atomic base -> CSR row starts; snapshot cnt; reset deg; dinv+g0
__global__ void k_scan_dinv_g0(const float* __restrict__ x, int n) {
    __shared__ int sh[1024];
    __shared__ int s_base;
    int tid = threadIdx.x;
    int i = blockIdx.x * 1024 + tid;
    int c = (i < n) ? g_deg[i] : 0;
    sh[tid] = c;
    __syncthreads();
    for (int off = 1; off < 1024; off <<= 1) {
        int v = (tid >= off) ? sh[tid - off] : 0;
        __syncthreads();
        sh[tid] += v;
        __syncthreads();
    }
    if (tid == 0) s_base = atomicAdd(&g_counter, sh[1023]);
    __syncthreads();
    int rs = s_base + sh[tid] - c;
    if (i < n) {
        g_row_start[i] = rs;
        g_cnt[i] = c;
        g_deg[i] = 0;                       // self-reset for next replay
        float di = rsqrtf((float)(c + 1));  // +1 self loop
        g_dinv[i] = di;
        const float4* x4 = (const float4*)x;
        float4 v0 = x4[2 * i], v1 = x4[2 * i + 1];
        g_g0[4 * i]     = make_float2(di * v0.x, di * v0.y);
        g_g0[4 * i + 1] = make_float2(di * v0.z, di * v0.w);
        g_g0[4 * i + 2] = make_float2(di * v1.x, di * v1.y);
        g_g0[4 * i + 3] = make_float2(di * v1.z, di * v1.w);
    }
}

// atomic-free scatter: position = row_start[dst] + rank[e]; resets counter
__global__ void k_scatter(const int* __restrict__ ei, int E) {
    int e = blockIdx.x * blockDim.x + threadIdx.x;
    if (e == 0) g_counter = 0;              // self-reset for next replay
    if (e >= E) return;
    int s = ei[e];
    int d = ei[E + e];
    g_col[g_row_start[d] + g_rank[e]] = s;
}

// ---------------------------------------------------------------------------
// Fused layer 1, 4 lanes per node. Cooperative index loading: per 8 edges,
// each lane loads an int2 of indices and shares via group-masked shfl
// (8x fewer index LDGs -> fewer L1 wavefronts, the measured bottleneck).
__global__ void __launch_bounds__(256)
k_agg1_gemm1(const float* __restrict__ W1, const float* __restrict__ b1, int n) {
    __shared__ float W1s[8 * 64];
    __shared__ float b1s[64];
    int tid = threadIdx.x;
    for (int t = tid; t < 512; t += blockDim.x) W1s[t] = W1[t];
    if (tid < 64) b1s[tid] = b1[tid];
    __syncthreads();

    int gtid = blockIdx.x * blockDim.x + tid;
    int node = gtid >> 2;
    int sub  = gtid & 3;
    if (node >= n) return;
    unsigned gmask = 0xFu << (tid & 28);    // this lane's 4-lane group

    // ---- aggregation: lane handles features [2*sub, 2*sub+1] ----
    float2 acc0 = g_g0[4 * node + sub];     // self loop
    float2 acc1 = make_float2(0.f, 0.f);
    float2 acc2 = make_float2(0.f, 0.f);
    float2 acc3 = make_float2(0.f, 0.f);
    int st = g_row_start[node];
    int cnt = g_cnt[node];
    const int* col = &g_col[st];
    int j = 0;
    if ((st & 1) && cnt >= 1) {             // align col[j] to 8B for int2 loads
        int s = col[0];
        float2 v = g_g0[4 * s + sub];
        acc0.x += v.x; acc0.y += v.y;
        j = 1;
    }
    for (; j + 8 <= cnt; j += 8) {
        int2 myi = *reinterpret_cast<const int2*>(&col[j + 2 * sub]);
        int s0 = __shfl_sync(gmask, myi.x, 0, 4);
        int s1 = __shfl_sync(gmask, myi.y, 0, 4);
        int s2 = __shfl_sync(gmask, myi.x, 1, 4);
        int s3 = __shfl_sync(gmask, myi.y, 1, 4);
        int s4 = __shfl_sync(gmask, myi.x, 2, 4);
        int s5 = __shfl_sync(gmask, myi.y, 2, 4);
        int s6 = __shfl_sync(gmask, myi.x, 3, 4);
        int s7 = __shfl_sync(gmask, myi.y, 3, 4);
        float2 v0 = g_g0[4 * s0 + sub];
        float2 v1 = g_g0[4 * s1 + sub];
        float2 v2 = g_g0[4 * s2 + sub];
        float2 v3 = g_g0[4 * s3 + sub];
        float2 v4 = g_g0[4 * s4 + sub];
        float2 v5 = g_g0[4 * s5 + sub];
        float2 v6 = g_g0[4 * s6 + sub];
        float2 v7 = g_g0[4 * s7 + sub];
        acc0.x += v0.x; acc0.y += v0.y;  acc1.x += v1.x; acc1.y += v1.y;
        acc2.x += v2.x; acc2.y += v2.y;  acc3.x += v3.x; acc3.y += v3.y;
        acc0.x += v4.x; acc0.y += v4.y;  acc1.x += v5.x; acc1.y += v5.y;
        acc2.x += v6.x; acc2.y += v6.y;  acc3.x += v7.x; acc3.y += v7.y;
    }
    for (; j < cnt; j++) {
        int s = col[j];
        float2 v = g_g0[4 * s + sub];
        acc0.x += v.x; acc0.y += v.y;
    }
    float di = g_dinv[node];
    float mx = di * ((acc0.x + acc1.x) + (acc2.x + acc3.x));
    float my = di * ((acc0.y + acc1.y) + (acc2.y + acc3.y));

    // ---- reassemble full 8-vector in every lane (group shfl) ----
    float a[8];
#pragma unroll
    for (int g = 0; g < 4; g++) {
        a[2 * g]     = __shfl_sync(gmask, mx, g, 4);
        a[2 * g + 1] = __shfl_sync(gmask, my, g, 4);
    }

    // ---- gemm1: this lane computes output cols [sub*16, sub*16+16) ----
    int cbase = sub * 16;
    float r[16];
#pragma unroll
    for (int c = 0; c < 16; c++) r[c] = b1s[cbase + c];
#pragma unroll
    for (int k = 0; k < 8; k++) {
        float ak = a[k];
        const float* wr = &W1s[k * 64 + cbase];
#pragma unroll
        for (int c = 0; c < 16; c++) r[c] += ak * wr[c];
    }
    __nv_bfloat162 ob[8];
#pragma unroll
    for (int t = 0; t < 8; t++)
        ob[t] = __float22bfloat162_rn(make_float2(di * fmaxf(r[2 * t], 0.f),
                                                  di * fmaxf(r[2 * t + 1], 0.f)));
    uint4* dst = (uint4*)&g_g1b[node * 32 + sub * 8];
    dst[0] = *reinterpret_cast<uint4*>(&ob[0]);
    dst[1] = *reinterpret_cast<uint4*>(&ob[4]);
}

// ---------------------------------------------------------------------------
// agg2: warp/node, unroll 8 with 4 independent accumulator chains (MLP~8).
__global__ void k_agg2(int n) {
    int gtid = blockIdx.x * blockDim.x + threadIdx.x;
    int node = gtid >> 5;
    int lane = gtid & 31;
    if (node >= n) return;
    float2 acc0 = __bfloat1622float2(g_g1b[node * 32 + lane]);   // self loop
    float2 acc1 = make_float2(0.f, 0.f);
    float2 acc2 = make_float2(0.f, 0.f);
    float2 acc3 = make_float2(0.f, 0.f);
    int st = g_row_start[node];
    int cnt = g_cnt[node];
    const int* col = &g_col[st];
    int j = 0;
    for (; j + 8 <= cnt; j += 8) {
        int s0 = col[j],     s1 = col[j + 1], s2 = col[j + 2], s3 = col[j + 3];
        int s4 = col[j + 4], s5 = col[j + 5], s6 = col[j + 6], s7 = col[j + 7];
        float2 v0 = __bfloat1622float2(g_g1b[s0 * 32 + lane]);
        float2 v1 = __bfloat1622float2(g_g1b[s1 * 32 + lane]);
        float2 v2 = __bfloat1622float2(g_g1b[s2 * 32 + lane]);
        float2 v3 = __bfloat1622float2(g_g1b[s3 * 32 + lane]);
        float2 v4 = __bfloat1622float2(g_g1b[s4 * 32 + lane]);
        float2 v5 = __bfloat1622float2(g_g1b[s5 * 32 + lane]);
        float2 v6 = __bfloat1622float2(g_g1b[s6 * 32 + lane]);
        float2 v7 = __bfloat1622float2(g_g1b[s7 * 32 + lane]);
        acc0.x += v0.x; acc0.y += v0.y;  acc1.x += v1.x; acc1.y += v1.y;
        acc2.x += v2.x; acc2.y += v2.y;  acc3.x += v3.x; acc3.y += v3.y;
        acc0.x += v4.x; acc0.y += v4.y;  acc1.x += v5.x; acc1.y += v5.y;
        acc2.x += v6.x; acc2.y += v6.y;  acc3.x += v7.x; acc3.y += v7.y;
    }
    if (j + 4 <= cnt) {
        int s0 = col[j], s1 = col[j + 1], s2 = col[j + 2], s3 = col[j + 3];
        float2 v0 = __bfloat1622float2(g_g1b[s0 * 32 + lane]);
        float2 v1 = __bfloat1622float2(g_g1b[s1 * 32 + lane]);
        float2 v2 = __bfloat1622float2(g_g1b[s2 * 32 + lane]);
        float2 v3 = __bfloat1622float2(g_g1b[s3 * 32 + lane]);
        acc0.x += v0.x; acc0.y += v0.y;  acc1.x += v1.x; acc1.y += v1.y;
        acc2.x += v2.x; acc2.y += v2.y;  acc3.x += v3.x; acc3.y += v3.y;
        j += 4;
    }
    for (; j < cnt; j++) {
        int s = col[j];
        float2 v = __bfloat1622float2(g_g1b[s * 32 + lane]);
        acc0.x += v.x; acc0.y += v.y;
    }
    float di = g_dinv[node];
    ((float2*)g_a2)[node * 32 + lane] =
        make_float2(di * (acc0.x + acc1.x + acc2.x + acc3.x),
                    di * (acc0.y + acc1.y + acc2.y + acc3.y));
}

// ---------------------------------------------------------------------------
// gemm2 + relu + Wfc dot + block reduction + fused final output (ticket).
__global__ void __launch_bounds__(256)
k_gemm2_reduce(const float* __restrict__ W2, const float* __restrict__ b2,
               const float* __restrict__ Wfc, const float* __restrict__ bfc,
               float* __restrict__ out, float invn, int n) {
    __shared__ float W2s[64 * 128];
    __shared__ float b2s[128];
    __shared__ float wfs[128];
    __shared__ float red[256];
    int tid = threadIdx.x;
    for (int t = tid; t < 2048; t += blockDim.x)
        ((float4*)W2s)[t] = ((const float4*)W2)[t];
    if (tid < 128) { b2s[tid] = b2[tid]; wfs[tid] = Wfc[tid]; }
    __syncthreads();

    int i = blockIdx.x * blockDim.x + tid;
    float nodesum = 0.0f;
    if (i < n) {
        float a[64];
        const float4* ar = &g_a2[i * 16];
#pragma unroll
        for (int t = 0; t < 16; t++) {
            float4 v = ar[t];
            a[4 * t] = v.x; a[4 * t + 1] = v.y; a[4 * t + 2] = v.z; a[4 * t + 3] = v.w;
        }
        for (int ch = 0; ch < 4; ch++) {
            unsigned long long acc[16];
#pragma unroll
            for (int t = 0; t < 16; t++) acc[t] = 0ull;
#pragma unroll
            for (int k = 0; k < 64; k++) {
                unsigned int au = __float_as_uint(a[k]);
                unsigned long long ap;
                asm("mov.b64 %0, {%1, %1};" : "=l"(ap) : "r"(au));
                const ulonglong2* w =
                    reinterpret_cast<const ulonglong2*>(&W2s[k * 128 + ch * 32]);
#pragma unroll
                for (int t = 0; t < 8; t++) {
                    ulonglong2 wv = w[t];
                    asm("fma.rn.f32x2 %0, %1, %2, %0;"
                        : "+l"(acc[2 * t]) : "l"(ap), "l"(wv.x));
                    asm("fma.rn.f32x2 %0, %1, %2, %0;"
                        : "+l"(acc[2 * t + 1]) : "l"(ap), "l"(wv.y));
                }
            }
#pragma unroll
            for (int u = 0; u < 16; u++) {
                unsigned int lo_u, hi_u;
                asm("mov.b64 {%0, %1}, %2;" : "=r"(lo_u), "=r"(hi_u) : "l"(acc[u]));
                int c = ch * 32 + 2 * u;
                float v0 = fmaxf(__uint_as_float(lo_u) + b2s[c], 0.0f);
                float v1 = fmaxf(__uint_as_float(hi_u) + b2s[c + 1], 0.0f);
                nodesum += v0 * wfs[c] + v1 * wfs[c + 1];
            }
        }
    }
    red[tid] = nodesum;
    __syncthreads();
    for (int off = 128; off > 0; off >>= 1) {
        if (tid < off) red[tid] += red[tid + off];
        __syncthreads();
    }
    if (tid == 0) {
        atomicAdd(&g_total, red[0]);
        __threadfence();
        int ticket = atomicAdd(&g_done, 1);
        if (ticket == (int)gridDim.x - 1) {           // last block finalizes
            float tot = atomicExch(&g_total, 0.0f);   // read + self-reset
            out[0] = tot * invn + bfc[0];
            g_done = 0;                               // self-reset
        }
    }
}

// ---------------------------------------------------------------------------
extern "C" void kernel_launch(void* const* d_in, const int* in_sizes, int n_in,
                              void* d_out, int out_size) {
    const float* x   = (const float*)d_in[0];
    const int*   ei  = (const int*)  d_in[1];
    const float* W1  = (const float*)d_in[2];
    const float* b1  = (const float*)d_in[3];
    const float* W2  = (const float*)d_in[4];
    const float* b2  = (const float*)d_in[5];
    const float* Wfc = (const float*)d_in[6];
    const float* bfc = (const float*)d_in[7];

    int n = in_sizes[0] / 8;
    int E = in_sizes[1] / 2;
    if (n > N_MAX) n = N_MAX;
    if (E > E_MAX) E = E_MAX;

    int nb  = (n + 255) / 256;
    int eb  = (E + 255) / 256;
    int sb  = (n + 1023) / 1024;
    int qb  = (n * 4 + 255) / 256;   // 4 lanes per node
    int wb  = (n * 32 + 255) / 256;  // warp per node

    k_hist        <<<eb, 256>>>(ei, E);
    k_scan_dinv_g0<<<sb, 1024>>>(x, n);
    k_scatter     <<<eb, 256>>>(ei, E);
    k_agg1_gemm1  <<<qb, 256>>>(W1, b1, n);
    k_agg2        <<<wb, 256>>>(n);
    k_gemm2_reduce<<<nb, 256>>>(W2, b2, Wfc, bfc, (float*)d_out,
                                1.0f / (float)n, n);
}

// round 8
// speedup vs baseline: 1.0785x; 1.0053x over previous
#include <cuda_runtime.h>
#include <cuda_bf16.h>
#include <cstdint>

// ---------------------------------------------------------------------------
// StressGNN: 2-layer GCN + mean readout + FC.
//   hist(deg+rank) -> scan(row_start,cnt,dinv,g0; deg self-reset) ->
//   scatter (atomic-free) -> [agg1+gemm1 fused, WARP per node, no divergence]
//   -> agg2 (warp/node MLP-8) -> [gemm2(FFMA2) + relu + Wfc-dot + reduce + final]
// Self-resetting device state => graph-replay deterministic.
// tcgen05 unavailable (harness lowers to .target sm_103, no 'a').
// ---------------------------------------------------------------------------

#define N_MAX 100000
#define E_MAX 1600000

__device__ int    g_deg[N_MAX];              // edge count (zeroed each cycle)
__device__ int    g_cnt[N_MAX];              // snapshot: in-edges per node
__device__ int    g_row_start[N_MAX];        // CSR row starts
__device__ int    g_rank[E_MAX];             // edge rank within dst bucket
__device__ int    g_col[E_MAX];              // src grouped by dst
__device__ float  g_dinv[N_MAX];             // (cnt+1)^-1/2
__device__ float  g_g0f[8 * N_MAX];          // dinv[i]*x[i]             [N,8]
__device__ __nv_bfloat162 g_g1b[32 * N_MAX]; // dinv[i]*relu(a1@W1+b1)   [N,64] bf16
__device__ float4 g_a2[16 * N_MAX];          // layer-2 aggregated input [N,64]
__device__ int    g_counter;
__device__ int    g_done;
__device__ float  g_total;

// ---------------------------------------------------------------------------
// histogram + record each edge's rank within its bucket (coalesced store)
__global__ void k_hist(const int* __restrict__ ei, int E) {
    int e = blockIdx.x * blockDim.x + threadIdx.x;
    if (e >= E) return;
    int d = ei[E + e];
    g_rank[e] = atomicAdd(&g_deg[d], 1);   // deg starts at 0 every replay
}

// block scan + atomic base -> CSR row starts; snapshot cnt; reset deg; dinv+g0
__global__ void k_scan_dinv_g0(const float* __restrict__ x, int n) {
    __shared__ int sh[1024];
    __shared__ int s_base;
    int tid = threadIdx.x;
    int i = blockIdx.x * 1024 + tid;
    int c = (i < n) ? g_deg[i] : 0;
    sh[tid] = c;
    __syncthreads();
    for (int off = 1; off < 1024; off <<= 1) {
        int v = (tid >= off) ? sh[tid - off] : 0;
        __syncthreads();
        sh[tid] += v;
        __syncthreads();
    }
    if (tid == 0) s_base = atomicAdd(&g_counter, sh[1023]);
    __syncthreads();
    int rs = s_base + sh[tid] - c;
    if (i < n) {
        g_row_start[i] = rs;
        g_cnt[i] = c;
        g_deg[i] = 0;                       // self-reset for next replay
        float di = rsqrtf((float)(c + 1));  // +1 self loop
        g_dinv[i] = di;
        const float4* x4 = (const float4*)x;
        float4 v0 = x4[2 * i], v1 = x4[2 * i + 1];
        float4* dst = (float4*)&g_g0f[8 * i];
        dst[0] = make_float4(di * v0.x, di * v0.y, di * v0.z, di * v0.w);
        dst[1] = make_float4(di * v1.x, di * v1.y, di * v1.z, di * v1.w);
    }
}

// atomic-free scatter: position = row_start[dst] + rank[e]; resets counter
__global__ void k_scatter(const int* __restrict__ ei, int E) {
    int e = blockIdx.x * blockDim.x + threadIdx.x;
    if (e == 0) g_counter = 0;              // self-reset for next replay
    if (e >= E) return;
    int s = ei[e];
    int d = ei[E + e];
    g_col[g_row_start[d] + g_rank[e]] = s;
}

// ---------------------------------------------------------------------------
// Fused layer 1, WARP per node (divergence-free: one trip count per warp).
// Lanes = 4 edge-slots x 8 features. Main loop: 16 edges/iter, 4 accumulator
// chains (MLP 4). Tails fully predicated. Cross-slot reduce = 2 shfl_xor.
__global__ void __launch_bounds__(256)
k_agg1_gemm1(const float* __restrict__ W1, const float* __restrict__ b1, int n) {
    __shared__ float W1s[8 * 64];
    __shared__ float b1s[64];
    int tid = threadIdx.x;
    for (int t = tid; t < 512; t += blockDim.x) W1s[t] = W1[t];
    if (tid < 64) b1s[tid] = b1[tid];
    __syncthreads();

    int wid  = tid >> 5;
    int lane = tid & 31;
    int node = blockIdx.x * 8 + wid;
    if (node >= n) return;

    int eslot = lane >> 3;      // 0..3: which edge in group of 4
    int feat  = lane & 7;       // 0..7: which feature

    int st  = g_row_start[node];
    int cnt = g_cnt[node];
    const int* col = &g_col[st];

    float acc0 = (eslot == 0) ? g_g0f[node * 8 + feat] : 0.0f;  // self loop
    float acc1 = 0.0f, acc2 = 0.0f, acc3 = 0.0f;
    int j = 0;
    for (; j + 16 <= cnt; j += 16) {
        int sa = col[j      + eslot];
        int sb = col[j + 4  + eslot];
        int sc = col[j + 8  + eslot];
        int sd = col[j + 12 + eslot];
        float va = g_g0f[sa * 8 + feat];
        float vb = g_g0f[sb * 8 + feat];
        float vc = g_g0f[sc * 8 + feat];
        float vd = g_g0f[sd * 8 + feat];
        acc0 += va; acc1 += vb; acc2 += vc; acc3 += vd;
    }
    if (j + 8 <= cnt) {
        int sa = col[j + eslot];
        int sb = col[j + 4 + eslot];
        float va = g_g0f[sa * 8 + feat];
        float vb = g_g0f[sb * 8 + feat];
        acc0 += va; acc1 += vb;
        j += 8;
    }
    if (j + eslot < cnt) {                 // predicated tail, 4 edges
        int s = col[j + eslot];
        acc2 += g_g0f[s * 8 + feat];
    }
    if (j + 4 + eslot < cnt) {             // predicated tail, 4 more
        int s = col[j + 4 + eslot];
        acc3 += g_g0f[s * 8 + feat];
    }
    float acc = (acc0 + acc1) + (acc2 + acc3);
    // reduce across the 4 edge-slots (same feat lives at lane strides of 8)
    acc += __shfl_xor_sync(0xffffffffu, acc, 8);
    acc += __shfl_xor_sync(0xffffffffu, acc, 16);

    float di = g_dinv[node];
    float av = di * acc;                   // a[feat], valid in every lane
    float a[8];
#pragma unroll
    for (int k = 0; k < 8; k++)
        a[k] = __shfl_sync(0xffffffffu, av, k);   // lane k holds feat k

    // gemm1: lane computes output cols [2*lane, 2*lane+1]
    float2 bb = *(const float2*)&b1s[2 * lane];
    float r0 = bb.x, r1 = bb.y;
#pragma unroll
    for (int k = 0; k < 8; k++) {
        float2 w = *(const float2*)&W1s[k * 64 + 2 * lane];
        r0 += a[k] * w.x;
        r1 += a[k] * w.y;
    }
    __nv_bfloat162 ob = __float22bfloat162_rn(
        make_float2(di * fmaxf(r0, 0.f), di * fmaxf(r1, 0.f)));
    ((uint32_t*)&g_g1b[node * 32])[lane] = *reinterpret_cast<uint32_t*>(&ob);
}

// ---------------------------------------------------------------------------
// agg2: warp/node, unroll 8 with 4 independent accumulator chains (MLP~8).
__global__ void k_agg2(int n) {
    int gtid = blockIdx.x * blockDim.x + threadIdx.x;
    int node = gtid >> 5;
    int lane = gtid & 31;
    if (node >= n) return;
    float2 acc0 = __bfloat1622float2(g_g1b[node * 32 + lane]);   // self loop
    float2 acc1 = make_float2(0.f, 0.f);
    float2 acc2 = make_float2(0.f, 0.f);
    float2 acc3 = make_float2(0.f, 0.f);
    int st = g_row_start[node];
    int cnt = g_cnt[node];
    const int* col = &g_col[st];
    int j = 0;
    for (; j + 8 <= cnt; j += 8) {
        int s0 = col[j],     s1 = col[j + 1], s2 = col[j + 2], s3 = col[j + 3];
        int s4 = col[j + 4], s5 = col[j + 5], s6 = col[j + 6], s7 = col[j + 7];
        float2 v0 = __bfloat1622float2(g_g1b[s0 * 32 + lane]);
        float2 v1 = __bfloat1622float2(g_g1b[s1 * 32 + lane]);
        float2 v2 = __bfloat1622float2(g_g1b[s2 * 32 + lane]);
        float2 v3 = __bfloat1622float2(g_g1b[s3 * 32 + lane]);
        float2 v4 = __bfloat1622float2(g_g1b[s4 * 32 + lane]);
        float2 v5 = __bfloat1622float2(g_g1b[s5 * 32 + lane]);
        float2 v6 = __bfloat1622float2(g_g1b[s6 * 32 + lane]);
        float2 v7 = __bfloat1622float2(g_g1b[s7 * 32 + lane]);
        acc0.x += v0.x; acc0.y += v0.y;  acc1.x += v1.x; acc1.y += v1.y;
        acc2.x += v2.x; acc2.y += v2.y;  acc3.x += v3.x; acc3.y += v3.y;
        acc0.x += v4.x; acc0.y += v4.y;  acc1.x += v5.x; acc1.y += v5.y;
        acc2.x += v6.x; acc2.y += v6.y;  acc3.x += v7.x; acc3.y += v7.y;
    }
    if (j + 4 <= cnt) {
        int s0 = col[j], s1 = col[j + 1], s2 = col[j + 2], s3 = col[j + 3];
        float2 v0 = __bfloat1622float2(g_g1b[s0 * 32 + lane]);
        float2 v1 = __bfloat1622float2(g_g1b[s1 * 32 + lane]);
        float2 v2 = __bfloat1622float2(g_g1b[s2 * 32 + lane]);
        float2 v3 = __bfloat1622float2(g_g1b[s3 * 32 + lane]);
        acc0.x += v0.x; acc0.y += v0.y;  acc1.x += v1.x; acc1.y += v1.y;
        acc2.x += v2.x; acc2.y += v2.y;  acc3.x += v3.x; acc3.y += v3.y;
        j += 4;
    }
    for (; j < cnt; j++) {
        int s = col[j];
        float2 v = __bfloat1622float2(g_g1b[s * 32 + lane]);
        acc0.x += v.x; acc0.y += v.y;
    }
    float di = g_dinv[node];
    ((float2*)g_a2)[node * 32 + lane] =
        make_float2(di * (acc0.x + acc1.x + acc2.x + acc3.x),
                    di * (acc0.y + acc1.y + acc2.y + acc3.y));
}

// ---------------------------------------------------------------------------
// gemm2 + relu + Wfc dot + block reduction + fused final output (ticket).
__global__ void __launch_bounds__(256)
k_gemm2_reduce(const float* __restrict__ W2, const float* __restrict__ b2,
               const float* __restrict__ Wfc, const float* __restrict__ bfc,
               float* __restrict__ out, float invn, int n) {
    __shared__ float W2s[64 * 128];
    __shared__ float b2s[128];
    __shared__ float wfs[128];
    __shared__ float red[256];
    int tid = threadIdx.x;
    for (int t = tid; t < 2048; t += blockDim.x)
        ((float4*)W2s)[t] = ((const float4*)W2)[t];
    if (tid < 128) { b2s[tid] = b2[tid]; wfs[tid] = Wfc[tid]; }
    __syncthreads();

    int i = blockIdx.x * blockDim.x + tid;
    float nodesum = 0.0f;
    if (i < n) {
        float a[64];
        const float4* ar = &g_a2[i * 16];
#pragma unroll
        for (int t = 0; t < 16; t++) {
            float4 v = ar[t];
            a[4 * t] = v.x; a[4 * t + 1] = v.y; a[4 * t + 2] = v.z; a[4 * t + 3] = v.w;
        }
        for (int ch = 0; ch < 4; ch++) {
            unsigned long long acc[16];
#pragma unroll
            for (int t = 0; t < 16; t++) acc[t] = 0ull;
#pragma unroll
            for (int k = 0; k < 64; k++) {
                unsigned int au = __float_as_uint(a[k]);
                unsigned long long ap;
                asm("mov.b64 %0, {%1, %1};" : "=l"(ap) : "r"(au));
                const ulonglong2* w =
                    reinterpret_cast<const ulonglong2*>(&W2s[k * 128 + ch * 32]);
#pragma unroll
                for (int t = 0; t < 8; t++) {
                    ulonglong2 wv = w[t];
                    asm("fma.rn.f32x2 %0, %1, %2, %0;"
                        : "+l"(acc[2 * t]) : "l"(ap), "l"(wv.x));
                    asm("fma.rn.f32x2 %0, %1, %2, %0;"
                        : "+l"(acc[2 * t + 1]) : "l"(ap), "l"(wv.y));
                }
            }
#pragma unroll
            for (int u = 0; u < 16; u++) {
                unsigned int lo_u, hi_u;
                asm("mov.b64 {%0, %1}, %2;" : "=r"(lo_u), "=r"(hi_u) : "l"(acc[u]));
                int c = ch * 32 + 2 * u;
                float v0 = fmaxf(__uint_as_float(lo_u) + b2s[c], 0.0f);
                float v1 = fmaxf(__uint_as_float(hi_u) + b2s[c + 1], 0.0f);
                nodesum += v0 * wfs[c] + v1 * wfs[c + 1];
            }
        }
    }
    red[tid] = nodesum;
    __syncthreads();
    for (int off = 128; off > 0; off >>= 1) {
        if (tid < off) red[tid] += red[tid + off];
        __syncthreads();
    }
    if (tid == 0) {
        atomicAdd(&g_total, red[0]);
        __threadfence();
        int ticket = atomicAdd(&g_done, 1);
        if (ticket == (int)gridDim.x - 1) {           // last block finalizes
            float tot = atomicExch(&g_total, 0.0f);   // read + self-reset
            out[0] = tot * invn + bfc[0];
            g_done = 0;                               // self-reset
        }
    }
}

// ---------------------------------------------------------------------------
extern "C" void kernel_launch(void* const* d_in, const int* in_sizes, int n_in,
                              void* d_out, int out_size) {
    const float* x   = (const float*)d_in[0];
    const int*   ei  = (const int*)  d_in[1];
    const float* W1  = (const float*)d_in[2];
    const float* b1  = (const float*)d_in[3];
    const float* W2  = (const float*)d_in[4];
    const float* b2  = (const float*)d_in[5];
    const float* Wfc = (const float*)d_in[6];
    const float* bfc = (const float*)d_in[7];

    int n = in_sizes[0] / 8;
    int E = in_sizes[1] / 2;
    if (n > N_MAX) n = N_MAX;
    if (E > E_MAX) E = E_MAX;

    int nb  = (n + 255) / 256;
    int eb  = (E + 255) / 256;
    int sb  = (n + 1023) / 1024;
    int ab  = (n + 7) / 8;           // warp per node, 8 warps/block
    int wb  = (n * 32 + 255) / 256;  // warp per node

    k_hist        <<<eb, 256>>>(ei, E);
    k_scan_dinv_g0<<<sb, 1024>>>(x, n);
    k_scatter     <<<eb, 256>>>(ei, E);
    k_agg1_gemm1  <<<ab, 256>>>(W1, b1, n);
    k_agg2        <<<wb, 256>>>(n);
    k_gemm2_reduce<<<nb, 256>>>(W2, b2, Wfc, bfc, (float*)d_out,
                                1.0f / (float)n, n);
}